// round 11
// baseline (speedup 1.0000x reference)
#include <cuda_runtime.h>

#define Bz   4
#define SEQ  2048
#define DIM  512
#define NH   8
#define HDIM 64

typedef unsigned long long ull;

// ---- packed f32x2 helpers (B300 FFMA2 path, PTX-only) ----------------------
__device__ __forceinline__ ull pk2(float x) {                 // (x, x)
    ull r; asm("mov.b64 %0, {%1, %1};" : "=l"(r) : "f"(x)); return r;
}
__device__ __forceinline__ void fma2(ull& d, ull a, ull b) {  // d += a*b (2x f32)
    asm("fma.rn.f32x2 %0, %1, %2, %0;" : "+l"(d) : "l"(a), "l"(b));
}
__device__ __forceinline__ float2 up2(ull v) {
    float2 r; asm("mov.b64 {%0, %1}, %2;" : "=f"(r.x), "=f"(r.y) : "l"(v)); return r;
}

// Scratch (device globals — no runtime allocation allowed).
__device__ float g_hq[(size_t)Bz * NH * SEQ * HDIM];   // [b][h][l][hd]
__device__ float g_hk[(size_t)Bz * NH * SEQ * HDIM];
__device__ float g_hv[(size_t)Bz * NH * SEQ * HDIM];
__device__ float g_av[(size_t)Bz * SEQ * DIM];         // [b][q][h*64+hd]

// ---------------------------------------------------------------------------
// GEMM body: 128x128 output tile, K-tile 32, 8x8 micro-tile, FFMA2.
// a_s/w_s are k-major transposed [32][132].
// ---------------------------------------------------------------------------
#define GEMM_TILE_LOOP(acc, a_s, w_s, tx, ty)                                   \
    _Pragma("unroll")                                                           \
    for (int kk = 0; kk < 32; kk++) {                                           \
        float4 a0 = *(const float4*)&a_s[kk * 132 + 8 * ty];                    \
        float4 a1 = *(const float4*)&a_s[kk * 132 + 8 * ty + 4];                \
        ulonglong2 w0 = *(const ulonglong2*)&w_s[kk * 132 + 8 * tx];            \
        ulonglong2 w1 = *(const ulonglong2*)&w_s[kk * 132 + 8 * tx + 4];        \
        ull q_[8] = {pk2(a0.x), pk2(a0.y), pk2(a0.z), pk2(a0.w),                \
                     pk2(a1.x), pk2(a1.y), pk2(a1.z), pk2(a1.w)};               \
        _Pragma("unroll")                                                       \
        for (int i = 0; i < 8; i++) {                                           \
            fma2(acc[i][0], q_[i], w0.x); fma2(acc[i][1], q_[i], w0.y);         \
            fma2(acc[i][2], q_[i], w1.x); fma2(acc[i][3], q_[i], w1.y);         \
        }                                                                       \
    }

// ---------------------------------------------------------------------------
// Projection: head = X @ W^T, output in [b][h][l][hd] layout. grid.z = q/k/v.
// grid = (DIM/128=4, 8192/128=64, 3), 256 threads.
// ---------------------------------------------------------------------------
__global__ __launch_bounds__(256, 2) void proj_kernel(
    const float* __restrict__ Xq, const float* __restrict__ Xk, const float* __restrict__ Xv,
    const float* __restrict__ Wq, const float* __restrict__ Wk, const float* __restrict__ Wv)
{
    __shared__ float a_s[32 * 132];
    __shared__ float w_s[32 * 132];

    const int z = blockIdx.z;
    const float* X = (z == 0) ? Xq : (z == 1) ? Xk : Xv;
    const float* W = (z == 0) ? Wq : (z == 1) ? Wk : Wv;
    float*     out = (z == 0) ? g_hq : (z == 1) ? g_hk : g_hv;

    const int n0  = blockIdx.x * 128;
    const int m0  = blockIdx.y * 128;
    const int tid = threadIdx.x;
    const int tx  = tid & 15, ty = tid >> 4;

    ull acc[8][4] = {};

    for (int k0 = 0; k0 < DIM; k0 += 32) {
        #pragma unroll
        for (int it = 0; it < 16; it++) {
            int e  = tid + it * 256;            // 0..4095
            int ki = e & 31, mi = e >> 5;       // coalesced over ki
            a_s[ki * 132 + mi] = X[(size_t)(m0 + mi) * DIM + k0 + ki];
            w_s[ki * 132 + mi] = W[(size_t)(n0 + mi) * DIM + k0 + ki];
        }
        __syncthreads();
        GEMM_TILE_LOOP(acc, a_s, w_s, tx, ty)
        __syncthreads();
    }

    // n-range of this thread: n0 + 8*tx .. +7, all inside one head
    const int h  = (n0 + 8 * tx) >> 6;
    const int hd = (8 * tx) & 63;
    #pragma unroll
    for (int i = 0; i < 8; i++) {
        int m = m0 + 8 * ty + i;
        int b = m >> 11, l = m & 2047;
        float2 e0 = up2(acc[i][0]), e1 = up2(acc[i][1]);
        float2 e2 = up2(acc[i][2]), e3 = up2(acc[i][3]);
        float* dst = &out[((size_t)(b * NH + h) * SEQ + l) * HDIM + hd];
        *(float4*)(dst)     = make_float4(e0.x, e0.y, e1.x, e1.y);
        *(float4*)(dst + 4) = make_float4(e2.x, e2.y, e3.x, e3.y);
    }
}

// ---------------------------------------------------------------------------
// Fused attention: 128-query tile per CTA, 64-key tiles, max-free softmax.
// S-phase: 8q x 4k per thread.  PV-phase: 8q x 4d per thread over 64 keys.
// ---------------------------------------------------------------------------
#define QS_F   (64 * 132)          // q_s  [64 d][132 r]
#define KS_F   (64 * 68)           // k_s  [64 d][68 c]
#define PS_F   (128 * 68)          // p_s  [128 r][68 c]  (row-major P)
#define VS_F   (64 * 68)           // v_s  [64 c][68 d]
#define ATTN_SMEM ((QS_F + KS_F + PS_F + VS_F) * 4 + 64 * 4)   // 103,936 B

__global__ __launch_bounds__(256, 2) void attn_kernel(const int* __restrict__ amask)
{
    extern __shared__ float sm[];
    float* q_s = sm;
    float* k_s = sm + QS_F;
    float* p_s = sm + QS_F + KS_F;
    float* v_s = sm + QS_F + KS_F + PS_F;
    int*   m_s = (int*)(sm + QS_F + KS_F + PS_F + VS_F);

    const int q0  = blockIdx.x * 128;
    const int h   = blockIdx.y;
    const int b   = blockIdx.z;
    const int tid = threadIdx.x;
    const int tx  = tid & 15, ty = tid >> 4;

    const float* qp = g_hq + (size_t)(b * NH + h) * SEQ * HDIM;
    const float* kp = g_hk + (size_t)(b * NH + h) * SEQ * HDIM;
    const float* vp = g_hv + (size_t)(b * NH + h) * SEQ * HDIM;

    // Q tile, d-major transposed, pre-scaled
    #pragma unroll
    for (int it = 0; it < 32; it++) {
        int e = tid + it * 256;                 // 0..8191
        int d = e & 63, r = e >> 6;
        q_s[d * 132 + r] = qp[(size_t)(q0 + r) * HDIM + d] * 0.125f;
    }

    ull   acc[8][2] = {};
    float lrow[8]   = {};

    for (int k0 = 0; k0 < SEQ; k0 += 64) {
        __syncthreads();   // prev PV done reading p_s/v_s; q_s visible (1st iter)
        #pragma unroll
        for (int it = 0; it < 16; it++) {
            int e = tid + it * 256;
            int d = e & 63, c = e >> 6;
            k_s[d * 68 + c] = kp[(size_t)(k0 + c) * HDIM + d];
            v_s[c * 68 + d] = vp[(size_t)(k0 + c) * HDIM + d];
        }
        if (tid < 64) m_s[tid] = amask[b * SEQ + k0 + tid];
        __syncthreads();

        // S = Q K^T : 8q x 4k per thread
        ull s2[8][2] = {};
        #pragma unroll
        for (int d = 0; d < 64; d++) {
            float4 qa = *(const float4*)&q_s[d * 132 + 8 * ty];
            float4 qb = *(const float4*)&q_s[d * 132 + 8 * ty + 4];
            ulonglong2 c2 = *(const ulonglong2*)&k_s[d * 68 + 4 * tx];
            ull qq[8] = {pk2(qa.x), pk2(qa.y), pk2(qa.z), pk2(qa.w),
                         pk2(qb.x), pk2(qb.y), pk2(qb.z), pk2(qb.w)};
            #pragma unroll
            for (int i = 0; i < 8; i++) {
                fma2(s2[i][0], qq[i], c2.x);
                fma2(s2[i][1], qq[i], c2.y);
            }
        }

        // exp + mask + partial row sums; write P row-major (STS.128)
        const bool dead0 = (m_s[4 * tx + 0] == 0);
        const bool dead1 = (m_s[4 * tx + 1] == 0);
        const bool dead2 = (m_s[4 * tx + 2] == 0);
        const bool dead3 = (m_s[4 * tx + 3] == 0);
        #pragma unroll
        for (int i = 0; i < 8; i++) {
            float2 lo = up2(s2[i][0]), hi = up2(s2[i][1]);
            float e0 = dead0 ? 0.f : __expf(lo.x);
            float e1 = dead1 ? 0.f : __expf(lo.y);
            float e2 = dead2 ? 0.f : __expf(hi.x);
            float e3 = dead3 ? 0.f : __expf(hi.y);
            lrow[i] += (e0 + e1) + (e2 + e3);
            *(float4*)&p_s[(8 * ty + i) * 68 + 4 * tx] = make_float4(e0, e1, e2, e3);
        }
        __syncthreads();

        // acc += P V : 8q x 4d per thread, 64 keys
        #pragma unroll
        for (int c = 0; c < 64; c++) {
            ulonglong2 v2 = *(const ulonglong2*)&v_s[c * 68 + 4 * tx];
            #pragma unroll
            for (int i = 0; i < 8; i++) {
                ull pv = pk2(p_s[(8 * ty + i) * 68 + c]);
                fma2(acc[i][0], pv, v2.x);
                fma2(acc[i][1], pv, v2.y);
            }
        }
    }

    #pragma unroll
    for (int i = 0; i < 8; i++) {
        float rs = lrow[i];
        rs += __shfl_xor_sync(0xffffffffu, rs, 1);
        rs += __shfl_xor_sync(0xffffffffu, rs, 2);
        rs += __shfl_xor_sync(0xffffffffu, rs, 4);
        rs += __shfl_xor_sync(0xffffffffu, rs, 8);
        float inv = 1.f / rs;
        int qrow  = q0 + 8 * ty + i;
        float2 lo = up2(acc[i][0]), hi = up2(acc[i][1]);
        *(float4*)&g_av[(size_t)(b * SEQ + qrow) * DIM + h * HDIM + 4 * tx] =
            make_float4(lo.x * inv, lo.y * inv, hi.x * inv, hi.y * inv);
    }
}

// ---------------------------------------------------------------------------
// Output projection: out = g_av @ Wo^T, 128x128x32 tiles.
// ---------------------------------------------------------------------------
__global__ __launch_bounds__(256, 2) void out_kernel(const float* __restrict__ W,
                                                     float* __restrict__ out)
{
    __shared__ float a_s[32 * 132];
    __shared__ float w_s[32 * 132];

    const int n0  = blockIdx.x * 128;
    const int m0  = blockIdx.y * 128;
    const int tid = threadIdx.x;
    const int tx  = tid & 15, ty = tid >> 4;

    ull acc[8][4] = {};

    for (int k0 = 0; k0 < DIM; k0 += 32) {
        #pragma unroll
        for (int it = 0; it < 16; it++) {
            int e  = tid + it * 256;
            int ki = e & 31, mi = e >> 5;
            a_s[ki * 132 + mi] = g_av[(size_t)(m0 + mi) * DIM + k0 + ki];
            w_s[ki * 132 + mi] = W[(size_t)(n0 + mi) * DIM + k0 + ki];
        }
        __syncthreads();
        GEMM_TILE_LOOP(acc, a_s, w_s, tx, ty)
        __syncthreads();
    }

    #pragma unroll
    for (int i = 0; i < 8; i++) {
        int m = m0 + 8 * ty + i;
        float2 e0 = up2(acc[i][0]), e1 = up2(acc[i][1]);
        float2 e2 = up2(acc[i][2]), e3 = up2(acc[i][3]);
        float* dst = &out[(size_t)m * DIM + n0 + 8 * tx];
        *(float4*)(dst)     = make_float4(e0.x, e0.y, e1.x, e1.y);
        *(float4*)(dst + 4) = make_float4(e2.x, e2.y, e3.x, e3.y);
    }
}

// ---------------------------------------------------------------------------
extern "C" void kernel_launch(void* const* d_in, const int* in_sizes, int n_in,
                              void* d_out, int out_size)
{
    const float* query = (const float*)d_in[0];
    const float* key   = (const float*)d_in[1];
    const float* value = (const float*)d_in[2];
    const float* Wq    = (const float*)d_in[3];
    const float* Wk    = (const float*)d_in[4];
    const float* Wv    = (const float*)d_in[5];
    const float* Wo    = (const float*)d_in[6];
    const int*   amask = (const int*)d_in[7];
    float*       out   = (float*)d_out;

    (void)in_sizes; (void)n_in; (void)out_size;

    proj_kernel<<<dim3(DIM / 128, (Bz * SEQ) / 128, 3), 256>>>(query, key, value,
                                                               Wq, Wk, Wv);

    cudaFuncSetAttribute(attn_kernel, cudaFuncAttributeMaxDynamicSharedMemorySize, ATTN_SMEM);
    attn_kernel<<<dim3(SEQ / 128, NH, Bz), 256, ATTN_SMEM>>>(amask);

    out_kernel<<<dim3(DIM / 128, (Bz * SEQ) / 128), 256>>>(Wo, out);
}

// round 12
// speedup vs baseline: 1.5666x; 1.5666x over previous
#include <cuda_runtime.h>
#include <cuda_bf16.h>

#define Bz   4
#define SEQ  2048
#define DIM  512
#define NH   8
#define HDIM 64

typedef unsigned int  u32;
typedef unsigned long long ull;

// ---- packed f32x2 helpers (kept for scalar GEMMs) ---------------------------
__device__ __forceinline__ ull pk2(float x) {
    ull r; asm("mov.b64 %0, {%1, %1};" : "=l"(r) : "f"(x)); return r;
}
__device__ __forceinline__ void fma2(ull& d, ull a, ull b) {
    asm("fma.rn.f32x2 %0, %1, %2, %0;" : "+l"(d) : "l"(a), "l"(b));
}
__device__ __forceinline__ float2 up2(ull v) {
    float2 r; asm("mov.b64 {%0, %1}, %2;" : "=f"(r.x), "=f"(r.y) : "l"(v)); return r;
}

// ---- bf16 helpers -----------------------------------------------------------
// pack (lo half = x, hi half = y)
__device__ __forceinline__ u32 bfpack(float x, float y) {
    u32 r; asm("cvt.rn.bf16x2.f32 %0, %1, %2;" : "=r"(r) : "f"(y), "f"(x)); return r;
}
__device__ __forceinline__ float bfround(float x) {
    return __bfloat162float(__float2bfloat16_rn(x));
}

// ---- mma.sync m16n8k16 bf16 (row.col, f32 accum) ----------------------------
__device__ __forceinline__ void mma_bf16(float* d, const u32* a, const u32* b) {
    asm("mma.sync.aligned.m16n8k16.row.col.f32.bf16.bf16.f32 "
        "{%0,%1,%2,%3}, {%4,%5,%6,%7}, {%8,%9}, {%0,%1,%2,%3};"
        : "+f"(d[0]), "+f"(d[1]), "+f"(d[2]), "+f"(d[3])
        : "r"(a[0]), "r"(a[1]), "r"(a[2]), "r"(a[3]), "r"(b[0]), "r"(b[1]));
}

// Scratch (device globals). bf16 hi/lo pairs stored as u32 (low half = even idx).
__device__ u32 g_qh[(size_t)Bz * NH * SEQ * 32];   // [b][h][q][d/2]   (Q * 0.125)
__device__ u32 g_ql[(size_t)Bz * NH * SEQ * 32];
__device__ u32 g_kh[(size_t)Bz * NH * SEQ * 32];   // [b][h][key][d/2]
__device__ u32 g_kl[(size_t)Bz * NH * SEQ * 32];
__device__ u32 g_vh[(size_t)Bz * NH * HDIM * 1024];// [b][h][d][key/2]  (V^T)
__device__ u32 g_vl[(size_t)Bz * NH * HDIM * 1024];
__device__ float g_av[(size_t)Bz * SEQ * DIM];     // attention out, fp32

// ---------------------------------------------------------------------------
// Scalar fp32 GEMM core (proven): 128x128 tile, K-tile 32, 8x8 micro, FFMA2.
// ---------------------------------------------------------------------------
#define GEMM_TILE_LOOP(acc, a_s, w_s, tx, ty)                                   \
    _Pragma("unroll")                                                           \
    for (int kk = 0; kk < 32; kk++) {                                           \
        float4 a0 = *(const float4*)&a_s[kk * 132 + 8 * ty];                    \
        float4 a1 = *(const float4*)&a_s[kk * 132 + 8 * ty + 4];                \
        ulonglong2 w0 = *(const ulonglong2*)&w_s[kk * 132 + 8 * tx];            \
        ulonglong2 w1 = *(const ulonglong2*)&w_s[kk * 132 + 8 * tx + 4];        \
        ull q_[8] = {pk2(a0.x), pk2(a0.y), pk2(a0.z), pk2(a0.w),                \
                     pk2(a1.x), pk2(a1.y), pk2(a1.z), pk2(a1.w)};               \
        _Pragma("unroll")                                                       \
        for (int i = 0; i < 8; i++) {                                           \
            fma2(acc[i][0], q_[i], w0.x); fma2(acc[i][1], q_[i], w0.y);         \
            fma2(acc[i][2], q_[i], w1.x); fma2(acc[i][3], q_[i], w1.y);         \
        }                                                                       \
    }

// ---------------------------------------------------------------------------
// Projection: head = X @ W^T with bf16 hi/lo split epilogue.
// z=0: Q (scaled 0.125) -> g_qh/g_ql ; z=1: K -> g_kh/g_kl ;
// z=2: V transposed     -> g_vh/g_vl ([d][key] pairs).
// ---------------------------------------------------------------------------
__global__ __launch_bounds__(256, 2) void proj_kernel(
    const float* __restrict__ Xq, const float* __restrict__ Xk, const float* __restrict__ Xv,
    const float* __restrict__ Wq, const float* __restrict__ Wk, const float* __restrict__ Wv)
{
    __shared__ float a_s[32 * 132];
    __shared__ float w_s[32 * 132];

    const int z = blockIdx.z;
    const float* X = (z == 0) ? Xq : (z == 1) ? Xk : Xv;
    const float* W = (z == 0) ? Wq : (z == 1) ? Wk : Wv;

    const int n0  = blockIdx.x * 128;
    const int m0  = blockIdx.y * 128;
    const int tid = threadIdx.x;
    const int tx  = tid & 15, ty = tid >> 4;

    ull acc[8][4] = {};

    for (int k0 = 0; k0 < DIM; k0 += 32) {
        #pragma unroll
        for (int it = 0; it < 16; it++) {
            int e  = tid + it * 256;
            int ki = e & 31, mi = e >> 5;
            a_s[ki * 132 + mi] = X[(size_t)(m0 + mi) * DIM + k0 + ki];
            w_s[ki * 132 + mi] = W[(size_t)(n0 + mi) * DIM + k0 + ki];
        }
        __syncthreads();
        GEMM_TILE_LOOP(acc, a_s, w_s, tx, ty)
        __syncthreads();
    }

    const int n  = n0 + 8 * tx;           // global out-feature base (8 wide)
    const int h  = n >> 6;                // head (constant per thread)
    const int hd = n & 63;                // head-local d base

    if (z < 2) {
        u32* oh = (z == 0) ? g_qh : g_kh;
        u32* ol = (z == 0) ? g_ql : g_kl;
        const float sc = (z == 0) ? 0.125f : 1.0f;
        #pragma unroll
        for (int i = 0; i < 8; i++) {
            int m = m0 + 8 * ty + i;
            int b = m >> 11, l = m & 2047;
            size_t base = ((size_t)(b * NH + h) * SEQ + l) * 32 + (hd >> 1);
            #pragma unroll
            for (int j = 0; j < 4; j++) {
                float2 v = up2(acc[i][j]);
                v.x *= sc; v.y *= sc;
                float hx = bfround(v.x), hy = bfround(v.y);
                oh[base + j] = bfpack(hx, hy);
                ol[base + j] = bfpack(v.x - hx, v.y - hy);
            }
        }
    } else {
        // V: unpack 8x8 micro-tile, store transposed [d][key] with key-pairs.
        float f[8][8];
        #pragma unroll
        for (int i = 0; i < 8; i++)
            #pragma unroll
            for (int j = 0; j < 4; j++) {
                float2 v = up2(acc[i][j]);
                f[i][2 * j] = v.x; f[i][2 * j + 1] = v.y;
            }
        int b     = m0 >> 11;
        int lbase = (m0 & 2047) + 8 * ty;     // key base (even)
        #pragma unroll
        for (int jd = 0; jd < 8; jd++) {
            int d = hd + jd;
            size_t rowb = ((size_t)(b * NH + h) * HDIM + d) * 1024 + (lbase >> 1);
            #pragma unroll
            for (int mp = 0; mp < 4; mp++) {
                float x = f[2 * mp][jd], y = f[2 * mp + 1][jd];
                float hx = bfround(x), hy = bfround(y);
                g_vh[rowb + mp] = bfpack(hx, hy);
                g_vl[rowb + mp] = bfpack(x - hx, y - hy);
            }
        }
    }
}

// ---------------------------------------------------------------------------
// Tensor-core attention: 128-q tile, 8 warps, warp = 16 q-rows x all keys.
// QK^T and PV via mma.sync bf16 with 2-term split (3 mma per logical mma).
// Max-free softmax (logits bounded ~50), quad-shfl row sums.
// ---------------------------------------------------------------------------
#define QROW 36                          // u32 row stride (conflict-free LDS)
#define ATTN_SMEM ((2 * 128 * QROW + 4 * 64 * QROW + 64) * 4)   // 73,984 B

__global__ __launch_bounds__(256, 2) void attn_kernel(const int* __restrict__ amask)
{
    extern __shared__ u32 smu[];
    u32* qh = smu;                        // [128][36]
    u32* ql = qh + 128 * QROW;
    u32* kh = ql + 128 * QROW;            // [64][36]
    u32* kl = kh + 64 * QROW;
    u32* vh = kl + 64 * QROW;             // [64][36]  V^T rows = d
    u32* vl = vh + 64 * QROW;
    int* m_s = (int*)(vl + 64 * QROW);    // [64]

    const int q0   = blockIdx.x * 128;
    const int h    = blockIdx.y;
    const int b    = blockIdx.z;
    const int tid  = threadIdx.x;
    const int w    = tid >> 5;
    const int lane = tid & 31;
    const int lr   = lane >> 2;           // 0..7
    const int lc   = lane & 3;            // 0..3
    const int r0   = 16 * w + lr;         // q-row (first)

    const size_t bh = (size_t)(b * NH + h);
    const size_t qb4 = (bh * SEQ + q0) * 8;        // uint4 index base
    const size_t kb4 = (bh * SEQ) * 8;
    const size_t vb4 = (bh * HDIM) * 256;

    // Load Q tile (bf16 hi/lo pairs), uint4 wide.
    #pragma unroll
    for (int it = 0; it < 4; it++) {
        int e = tid + it * 256;                    // 0..1023
        int row = e >> 3, c4 = e & 7;
        *(uint4*)&qh[row * QROW + 4 * c4] = ((const uint4*)g_qh)[qb4 + e];
        *(uint4*)&ql[row * QROW + 4 * c4] = ((const uint4*)g_ql)[qb4 + e];
    }

    float o[8][4] = {};                   // O accum: 8 d-tiles x (2 rows x 2 cols)
    float lrow0 = 0.f, lrow1 = 0.f;

    for (int kt = 0; kt < SEQ / 64; kt++) {
        __syncthreads();
        #pragma unroll
        for (int it = 0; it < 2; it++) {
            int e = tid + it * 256;                // 0..511
            int row = e >> 3, c4 = e & 7;
            *(uint4*)&kh[row * QROW + 4 * c4] = ((const uint4*)g_kh)[kb4 + kt * 512 + e];
            *(uint4*)&kl[row * QROW + 4 * c4] = ((const uint4*)g_kl)[kb4 + kt * 512 + e];
            *(uint4*)&vh[row * QROW + 4 * c4] = ((const uint4*)g_vh)[vb4 + row * 256 + kt * 8 + c4];
            *(uint4*)&vl[row * QROW + 4 * c4] = ((const uint4*)g_vl)[vb4 + row * 256 + kt * 8 + c4];
        }
        if (tid < 64) m_s[tid] = amask[b * SEQ + kt * 64 + tid];
        __syncthreads();

        // ---- S = Q K^T : 8 n8 key-tiles, k = 64 (4 chunks), 3-way split ----
        float s[8][4] = {};
        #pragma unroll
        for (int c = 0; c < 4; c++) {
            u32 aH[4], aL[4];
            aH[0] = qh[r0 * QROW + 8 * c + lc];
            aH[1] = qh[(r0 + 8) * QROW + 8 * c + lc];
            aH[2] = qh[r0 * QROW + 8 * c + 4 + lc];
            aH[3] = qh[(r0 + 8) * QROW + 8 * c + 4 + lc];
            aL[0] = ql[r0 * QROW + 8 * c + lc];
            aL[1] = ql[(r0 + 8) * QROW + 8 * c + lc];
            aL[2] = ql[r0 * QROW + 8 * c + 4 + lc];
            aL[3] = ql[(r0 + 8) * QROW + 8 * c + 4 + lc];
            #pragma unroll
            for (int t = 0; t < 8; t++) {
                int krow = (8 * t + lr) * QROW;
                u32 bH[2] = { kh[krow + 8 * c + lc], kh[krow + 8 * c + 4 + lc] };
                u32 bL[2] = { kl[krow + 8 * c + lc], kl[krow + 8 * c + 4 + lc] };
                mma_bf16(s[t], aH, bH);
                mma_bf16(s[t], aH, bL);
                mma_bf16(s[t], aL, bH);
            }
        }

        // ---- exp + mask + row sums + bf16-split P (in registers) ----
        u32 pH0[8], pH1[8], pL0[8], pL1[8];
        #pragma unroll
        for (int t = 0; t < 8; t++) {
            int c0 = 8 * t + 2 * lc;
            bool d0 = (m_s[c0] == 0), d1 = (m_s[c0 + 1] == 0);
            float p0 = d0 ? 0.f : __expf(s[t][0]);
            float p1 = d1 ? 0.f : __expf(s[t][1]);
            float p2 = d0 ? 0.f : __expf(s[t][2]);
            float p3 = d1 ? 0.f : __expf(s[t][3]);
            lrow0 += p0 + p1;
            lrow1 += p2 + p3;
            float h0 = bfround(p0), h1 = bfround(p1);
            float h2 = bfround(p2), h3 = bfround(p3);
            pH0[t] = bfpack(h0, h1);           pH1[t] = bfpack(h2, h3);
            pL0[t] = bfpack(p0 - h0, p1 - h1); pL1[t] = bfpack(p2 - h2, p3 - h3);
        }

        // ---- O += P V : A from registers (C-layout == A-layout), B = V^T ----
        #pragma unroll
        for (int c = 0; c < 4; c++) {
            u32 aH[4] = { pH0[2 * c], pH1[2 * c], pH0[2 * c + 1], pH1[2 * c + 1] };
            u32 aL[4] = { pL0[2 * c], pL1[2 * c], pL0[2 * c + 1], pL1[2 * c + 1] };
            #pragma unroll
            for (int t = 0; t < 8; t++) {
                int vrow = (8 * t + lr) * QROW;
                u32 bH[2] = { vh[vrow + 8 * c + lc], vh[vrow + 8 * c + 4 + lc] };
                u32 bL[2] = { vl[vrow + 8 * c + lc], vl[vrow + 8 * c + 4 + lc] };
                mma_bf16(o[t], aH, bH);
                mma_bf16(o[t], aH, bL);
                mma_bf16(o[t], aL, bH);
            }
        }
    }

    // row-sum reduce over the quad (lanes sharing lr)
    lrow0 += __shfl_xor_sync(0xffffffffu, lrow0, 1);
    lrow0 += __shfl_xor_sync(0xffffffffu, lrow0, 2);
    lrow1 += __shfl_xor_sync(0xffffffffu, lrow1, 1);
    lrow1 += __shfl_xor_sync(0xffffffffu, lrow1, 2);
    float inv0 = 1.f / lrow0, inv1 = 1.f / lrow1;

    float* av0 = &g_av[(size_t)(b * SEQ + q0 + r0) * DIM + h * HDIM];
    float* av1 = &g_av[(size_t)(b * SEQ + q0 + r0 + 8) * DIM + h * HDIM];
    #pragma unroll
    for (int t = 0; t < 8; t++) {
        int col = 8 * t + 2 * lc;
        *(float2*)&av0[col] = make_float2(o[t][0] * inv0, o[t][1] * inv0);
        *(float2*)&av1[col] = make_float2(o[t][2] * inv1, o[t][3] * inv1);
    }
}

// ---------------------------------------------------------------------------
// Output projection: out = g_av @ Wo^T (scalar fp32, proven).
// ---------------------------------------------------------------------------
__global__ __launch_bounds__(256, 2) void out_kernel(const float* __restrict__ W,
                                                     float* __restrict__ out)
{
    __shared__ float a_s[32 * 132];
    __shared__ float w_s[32 * 132];

    const int n0  = blockIdx.x * 128;
    const int m0  = blockIdx.y * 128;
    const int tid = threadIdx.x;
    const int tx  = tid & 15, ty = tid >> 4;

    ull acc[8][4] = {};

    for (int k0 = 0; k0 < DIM; k0 += 32) {
        #pragma unroll
        for (int it = 0; it < 16; it++) {
            int e  = tid + it * 256;
            int ki = e & 31, mi = e >> 5;
            a_s[ki * 132 + mi] = g_av[(size_t)(m0 + mi) * DIM + k0 + ki];
            w_s[ki * 132 + mi] = W[(size_t)(n0 + mi) * DIM + k0 + ki];
        }
        __syncthreads();
        GEMM_TILE_LOOP(acc, a_s, w_s, tx, ty)
        __syncthreads();
    }

    #pragma unroll
    for (int i = 0; i < 8; i++) {
        int m = m0 + 8 * ty + i;
        float2 e0 = up2(acc[i][0]), e1 = up2(acc[i][1]);
        float2 e2 = up2(acc[i][2]), e3 = up2(acc[i][3]);
        float* dst = &out[(size_t)m * DIM + n0 + 8 * tx];
        *(float4*)(dst)     = make_float4(e0.x, e0.y, e1.x, e1.y);
        *(float4*)(dst + 4) = make_float4(e2.x, e2.y, e3.x, e3.y);
    }
}

// ---------------------------------------------------------------------------
extern "C" void kernel_launch(void* const* d_in, const int* in_sizes, int n_in,
                              void* d_out, int out_size)
{
    const float* query = (const float*)d_in[0];
    const float* key   = (const float*)d_in[1];
    const float* value = (const float*)d_in[2];
    const float* Wq    = (const float*)d_in[3];
    const float* Wk    = (const float*)d_in[4];
    const float* Wv    = (const float*)d_in[5];
    const float* Wo    = (const float*)d_in[6];
    const int*   amask = (const int*)d_in[7];
    float*       out   = (float*)d_out;

    (void)in_sizes; (void)n_in; (void)out_size;

    proj_kernel<<<dim3(DIM / 128, (Bz * SEQ) / 128, 3), 256>>>(query, key, value,
                                                               Wq, Wk, Wv);

    cudaFuncSetAttribute(attn_kernel, cudaFuncAttributeMaxDynamicSharedMemorySize, ATTN_SMEM);
    attn_kernel<<<dim3(SEQ / 128, NH, Bz), 256, ATTN_SMEM>>>(amask);

    out_kernel<<<dim3(DIM / 128, (Bz * SEQ) / 128), 256>>>(Wo, out);
}

// round 13
// speedup vs baseline: 2.4142x; 1.5411x over previous
#include <cuda_runtime.h>
#include <cuda_bf16.h>

#define Bz   4
#define SEQ  2048
#define DIM  512
#define NH   8
#define HDIM 64

typedef unsigned int u32;

#define XSZ (8192 * 256)   // u32 pairs per X tensor (8192 rows x 256 d-pairs)
#define WSZ (512 * 256)    // u32 pairs per W tensor

// ---- bf16 helpers -----------------------------------------------------------
__device__ __forceinline__ u32 bfpack(float x, float y) {   // lo half = x
    u32 r; asm("cvt.rn.bf16x2.f32 %0, %1, %2;" : "=r"(r) : "f"(y), "f"(x)); return r;
}
__device__ __forceinline__ float bfround(float x) {
    return __bfloat162float(__float2bfloat16_rn(x));
}
__device__ __forceinline__ void split2(float x, float y, u32& h, u32& l) {
    float hx = bfround(x), hy = bfround(y);
    h = bfpack(hx, hy);
    l = bfpack(x - hx, y - hy);
}

// ---- mma.sync m16n8k16 bf16 (row.col, f32 accum) ----------------------------
__device__ __forceinline__ void mma_bf16(float* d, const u32* a, const u32* b) {
    asm("mma.sync.aligned.m16n8k16.row.col.f32.bf16.bf16.f32 "
        "{%0,%1,%2,%3}, {%4,%5,%6,%7}, {%8,%9}, {%0,%1,%2,%3};"
        : "+f"(d[0]), "+f"(d[1]), "+f"(d[2]), "+f"(d[3])
        : "r"(a[0]), "r"(a[1]), "r"(a[2]), "r"(a[3]), "r"(b[0]), "r"(b[1]));
}

// ---- device-global scratch (no runtime allocation) --------------------------
__device__ u32 g_xh[(size_t)3 * XSZ], g_xl[(size_t)3 * XSZ];   // split X q/k/v
__device__ u32 g_wh[(size_t)4 * WSZ], g_wl[(size_t)4 * WSZ];   // split Wq,Wk,Wv,Wo
__device__ u32 g_qh[(size_t)Bz * NH * SEQ * 32];   // [b][h][q][d/2]  (x0.125)
__device__ u32 g_ql[(size_t)Bz * NH * SEQ * 32];
__device__ u32 g_kh[(size_t)Bz * NH * SEQ * 32];   // [b][h][key][d/2]
__device__ u32 g_kl[(size_t)Bz * NH * SEQ * 32];
__device__ u32 g_vh[(size_t)Bz * NH * HDIM * 1024];// [b][h][d][key/2] (V^T)
__device__ u32 g_vl[(size_t)Bz * NH * HDIM * 1024];
__device__ u32 g_avh[(size_t)8192 * 256];          // attn out, [m][d-pair]
__device__ u32 g_avl[(size_t)8192 * 256];

// ---------------------------------------------------------------------------
// Split pre-pass: fp32 -> packed bf16 hi/lo pair arrays. One thread = 8 floats.
// grid = (2048, 7): y = {Xq,Xk,Xv,Wq,Wk,Wv,Wo}
// ---------------------------------------------------------------------------
__global__ __launch_bounds__(256) void split_kernel(
    const float* __restrict__ Xq, const float* __restrict__ Xk,
    const float* __restrict__ Xv, const float* __restrict__ Wq,
    const float* __restrict__ Wk, const float* __restrict__ Wv,
    const float* __restrict__ Wo)
{
    const int z = blockIdx.y;
    const float* src; u32 *dh, *dl; int n8;
    if (z < 3) {
        src = (z == 0) ? Xq : (z == 1) ? Xk : Xv;
        dh = g_xh + (size_t)z * XSZ; dl = g_xl + (size_t)z * XSZ;
        n8 = (8192 * 512) / 8;
    } else {
        int i = z - 3;
        src = (i == 0) ? Wq : (i == 1) ? Wk : (i == 2) ? Wv : Wo;
        dh = g_wh + (size_t)i * WSZ; dl = g_wl + (size_t)i * WSZ;
        n8 = (512 * 512) / 8;
    }
    int g = blockIdx.x * 256 + threadIdx.x;
    if (g >= n8) return;
    const float4* s4 = (const float4*)src;
    float4 f0 = s4[2 * g], f1 = s4[2 * g + 1];
    uint4 H, L;
    split2(f0.x, f0.y, H.x, L.x);
    split2(f0.z, f0.w, H.y, L.y);
    split2(f1.x, f1.y, H.z, L.z);
    split2(f1.z, f1.w, H.w, L.w);
    ((uint4*)dh)[g] = H;
    ((uint4*)dl)[g] = L;
}

// ---------------------------------------------------------------------------
// GEMM core: C[128,128] = A @ B^T over k=512, bf16 3-way split mma.
// A/B stored as [row][k-pair] u32. k-tile 64 (8 uint4/row), smem stride 36 u32
// (conflict-free, validated in attention kernel). 8 warps x (16 m x 128 n).
// ---------------------------------------------------------------------------
#define GEMM_SMEM (4 * 128 * 36 * 4)   // 73,728 B

__device__ __forceinline__ void gemm_core(
    const uint4* __restrict__ A4h, const uint4* __restrict__ A4l,
    const uint4* __restrict__ B4h, const uint4* __restrict__ B4l,
    u32* sAh, u32* sAl, u32* sBh, u32* sBl, float c[16][4])
{
    const int tid  = threadIdx.x;
    const int w    = tid >> 5;
    const int lane = tid & 31;
    const int lr   = lane >> 2, lc = lane & 3;
    const int r0   = 16 * w + lr;

    for (int kt = 0; kt < 8; kt++) {
        __syncthreads();
        #pragma unroll
        for (int it = 0; it < 4; it++) {
            int e   = tid + it * 256;          // 0..1023
            int row = e >> 3, c4 = e & 7;
            int so  = row * 36 + 4 * c4;
            size_t go = (size_t)row * 64 + kt * 8 + c4;
            *(uint4*)&sAh[so] = A4h[go];
            *(uint4*)&sAl[so] = A4l[go];
            *(uint4*)&sBh[so] = B4h[go];
            *(uint4*)&sBl[so] = B4l[go];
        }
        __syncthreads();
        #pragma unroll
        for (int ch = 0; ch < 4; ch++) {
            u32 aH[4], aL[4];
            int ab = r0 * 36 + 8 * ch + lc;
            aH[0] = sAh[ab];     aH[1] = sAh[ab + 8 * 36];
            aH[2] = sAh[ab + 4]; aH[3] = sAh[ab + 4 + 8 * 36];
            aL[0] = sAl[ab];     aL[1] = sAl[ab + 8 * 36];
            aL[2] = sAl[ab + 4]; aL[3] = sAl[ab + 4 + 8 * 36];
            #pragma unroll
            for (int t = 0; t < 16; t++) {
                int bb = (8 * t + lr) * 36 + 8 * ch + lc;
                u32 bH[2] = { sBh[bb], sBh[bb + 4] };
                u32 bL[2] = { sBl[bb], sBl[bb + 4] };
                mma_bf16(c[t], aH, bH);
                mma_bf16(c[t], aH, bL);
                mma_bf16(c[t], aL, bH);
            }
        }
    }
}

// ---------------------------------------------------------------------------
// Projections. z<2: C = X_z @ W_z^T (m = tokens, n = features) -> Q/K split.
// z==2: C = Wv @ Xv^T (m = d-features, n = keys) -> V^T split, key-pairs free.
// ---------------------------------------------------------------------------
__global__ __launch_bounds__(256, 2) void proj_mma()
{
    extern __shared__ u32 sm[];
    u32* sAh = sm;
    u32* sAl = sAh + 128 * 36;
    u32* sBh = sAl + 128 * 36;
    u32* sBl = sBh + 128 * 36;

    const int z = blockIdx.z;
    int m0, n0;
    const u32 *Ah, *Al, *Bh, *Bl;
    if (z < 2) {
        m0 = blockIdx.y * 128; n0 = blockIdx.x * 128;
        Ah = g_xh + (size_t)z * XSZ; Al = g_xl + (size_t)z * XSZ;
        Bh = g_wh + (size_t)z * WSZ; Bl = g_wl + (size_t)z * WSZ;
    } else {
        m0 = blockIdx.x * 128; n0 = blockIdx.y * 128;
        Ah = g_wh + (size_t)2 * WSZ; Al = g_wl + (size_t)2 * WSZ;
        Bh = g_xh + (size_t)2 * XSZ; Bl = g_xl + (size_t)2 * XSZ;
    }

    float c[16][4] = {};
    gemm_core((const uint4*)Ah + (size_t)m0 * 64, (const uint4*)Al + (size_t)m0 * 64,
              (const uint4*)Bh + (size_t)n0 * 64, (const uint4*)Bl + (size_t)n0 * 64,
              sAh, sAl, sBh, sBl, c);

    const int tid = threadIdx.x, w = tid >> 5, lane = tid & 31;
    const int lr = lane >> 2, lc = lane & 3;

    if (z < 2) {
        u32* oh = z ? g_kh : g_qh;
        u32* ol = z ? g_kl : g_ql;
        const float sc = z ? 1.0f : 0.125f;
        #pragma unroll
        for (int t = 0; t < 16; t++) {
            int ng = n0 + 8 * t + 2 * lc;
            int h = ng >> 6, pidx = (ng & 63) >> 1;
            #pragma unroll
            for (int half = 0; half < 2; half++) {
                int m = m0 + 16 * w + lr + 8 * half;
                int b = m >> 11, l = m & 2047;
                size_t base = ((size_t)(b * NH + h) * SEQ + l) * 32 + pidx;
                u32 H, L;
                split2(c[t][2 * half] * sc, c[t][2 * half + 1] * sc, H, L);
                oh[base] = H; ol[base] = L;
            }
        }
    } else {
        #pragma unroll
        for (int t = 0; t < 16; t++) {
            int kg = n0 + 8 * t + 2 * lc;        // even key index
            int b = kg >> 11, l = kg & 2047;
            #pragma unroll
            for (int half = 0; half < 2; half++) {
                int dg = m0 + 16 * w + lr + 8 * half;
                int h = dg >> 6, hd = dg & 63;
                size_t base = ((size_t)(b * NH + h) * HDIM + hd) * 1024 + (l >> 1);
                u32 H, L;
                split2(c[t][2 * half], c[t][2 * half + 1], H, L);
                g_vh[base] = H; g_vl[base] = L;
            }
        }
    }
}

// ---------------------------------------------------------------------------
// Tensor-core attention (validated R12); epilogue now emits split bf16 pairs.
// ---------------------------------------------------------------------------
#define QROW 36
#define ATTN_SMEM ((2 * 128 * QROW + 4 * 64 * QROW + 64) * 4)   // 73,984 B

__global__ __launch_bounds__(256, 2) void attn_kernel(const int* __restrict__ amask)
{
    extern __shared__ u32 smu[];
    u32* qh = smu;
    u32* ql = qh + 128 * QROW;
    u32* kh = ql + 128 * QROW;
    u32* kl = kh + 64 * QROW;
    u32* vh = kl + 64 * QROW;
    u32* vl = vh + 64 * QROW;
    int* m_s = (int*)(vl + 64 * QROW);

    const int q0   = blockIdx.x * 128;
    const int h    = blockIdx.y;
    const int b    = blockIdx.z;
    const int tid  = threadIdx.x;
    const int w    = tid >> 5;
    const int lane = tid & 31;
    const int lr   = lane >> 2, lc = lane & 3;
    const int r0   = 16 * w + lr;

    const size_t bh  = (size_t)(b * NH + h);
    const size_t qb4 = (bh * SEQ + q0) * 8;
    const size_t kb4 = (bh * SEQ) * 8;
    const size_t vb4 = (bh * HDIM) * 256;

    #pragma unroll
    for (int it = 0; it < 4; it++) {
        int e = tid + it * 256;
        int row = e >> 3, c4 = e & 7;
        *(uint4*)&qh[row * QROW + 4 * c4] = ((const uint4*)g_qh)[qb4 + e];
        *(uint4*)&ql[row * QROW + 4 * c4] = ((const uint4*)g_ql)[qb4 + e];
    }

    float o[8][4] = {};
    float lrow0 = 0.f, lrow1 = 0.f;

    for (int kt = 0; kt < SEQ / 64; kt++) {
        __syncthreads();
        #pragma unroll
        for (int it = 0; it < 2; it++) {
            int e = tid + it * 256;
            int row = e >> 3, c4 = e & 7;
            *(uint4*)&kh[row * QROW + 4 * c4] = ((const uint4*)g_kh)[kb4 + kt * 512 + e];
            *(uint4*)&kl[row * QROW + 4 * c4] = ((const uint4*)g_kl)[kb4 + kt * 512 + e];
            *(uint4*)&vh[row * QROW + 4 * c4] = ((const uint4*)g_vh)[vb4 + row * 256 + kt * 8 + c4];
            *(uint4*)&vl[row * QROW + 4 * c4] = ((const uint4*)g_vl)[vb4 + row * 256 + kt * 8 + c4];
        }
        if (tid < 64) m_s[tid] = amask[b * SEQ + kt * 64 + tid];
        __syncthreads();

        // S = Q K^T
        float s[8][4] = {};
        #pragma unroll
        for (int c = 0; c < 4; c++) {
            u32 aH[4], aL[4];
            int ab = r0 * QROW + 8 * c + lc;
            aH[0] = qh[ab];     aH[1] = qh[ab + 8 * QROW];
            aH[2] = qh[ab + 4]; aH[3] = qh[ab + 4 + 8 * QROW];
            aL[0] = ql[ab];     aL[1] = ql[ab + 8 * QROW];
            aL[2] = ql[ab + 4]; aL[3] = ql[ab + 4 + 8 * QROW];
            #pragma unroll
            for (int t = 0; t < 8; t++) {
                int krow = (8 * t + lr) * QROW;
                u32 bH[2] = { kh[krow + 8 * c + lc], kh[krow + 8 * c + 4 + lc] };
                u32 bL[2] = { kl[krow + 8 * c + lc], kl[krow + 8 * c + 4 + lc] };
                mma_bf16(s[t], aH, bH);
                mma_bf16(s[t], aH, bL);
                mma_bf16(s[t], aL, bH);
            }
        }

        // exp + mask + row sums + register P split
        u32 pH0[8], pH1[8], pL0[8], pL1[8];
        #pragma unroll
        for (int t = 0; t < 8; t++) {
            int c0 = 8 * t + 2 * lc;
            bool d0 = (m_s[c0] == 0), d1 = (m_s[c0 + 1] == 0);
            float p0 = d0 ? 0.f : __expf(s[t][0]);
            float p1 = d1 ? 0.f : __expf(s[t][1]);
            float p2 = d0 ? 0.f : __expf(s[t][2]);
            float p3 = d1 ? 0.f : __expf(s[t][3]);
            lrow0 += p0 + p1;
            lrow1 += p2 + p3;
            float h0 = bfround(p0), h1 = bfround(p1);
            float h2 = bfround(p2), h3 = bfround(p3);
            pH0[t] = bfpack(h0, h1);           pH1[t] = bfpack(h2, h3);
            pL0[t] = bfpack(p0 - h0, p1 - h1); pL1[t] = bfpack(p2 - h2, p3 - h3);
        }

        // O += P V
        #pragma unroll
        for (int c = 0; c < 4; c++) {
            u32 aH[4] = { pH0[2 * c], pH1[2 * c], pH0[2 * c + 1], pH1[2 * c + 1] };
            u32 aL[4] = { pL0[2 * c], pL1[2 * c], pL0[2 * c + 1], pL1[2 * c + 1] };
            #pragma unroll
            for (int t = 0; t < 8; t++) {
                int vrow = (8 * t + lr) * QROW;
                u32 bH[2] = { vh[vrow + 8 * c + lc], vh[vrow + 8 * c + 4 + lc] };
                u32 bL[2] = { vl[vrow + 8 * c + lc], vl[vrow + 8 * c + 4 + lc] };
                mma_bf16(o[t], aH, bH);
                mma_bf16(o[t], aH, bL);
                mma_bf16(o[t], aL, bH);
            }
        }
    }

    lrow0 += __shfl_xor_sync(0xffffffffu, lrow0, 1);
    lrow0 += __shfl_xor_sync(0xffffffffu, lrow0, 2);
    lrow1 += __shfl_xor_sync(0xffffffffu, lrow1, 1);
    lrow1 += __shfl_xor_sync(0xffffffffu, lrow1, 2);
    float inv0 = 1.f / lrow0, inv1 = 1.f / lrow1;

    const size_t a0 = (size_t)(b * SEQ + q0 + r0) * 256 + h * 32;
    const size_t a1 = (size_t)(b * SEQ + q0 + r0 + 8) * 256 + h * 32;
    #pragma unroll
    for (int t = 0; t < 8; t++) {
        u32 H, L;
        split2(o[t][0] * inv0, o[t][1] * inv0, H, L);
        g_avh[a0 + 4 * t + lc] = H; g_avl[a0 + 4 * t + lc] = L;
        split2(o[t][2] * inv1, o[t][3] * inv1, H, L);
        g_avh[a1 + 4 * t + lc] = H; g_avl[a1 + 4 * t + lc] = L;
    }
}

// ---------------------------------------------------------------------------
// Output projection: out = attn_vec @ Wo^T, fp32 epilogue.
// ---------------------------------------------------------------------------
__global__ __launch_bounds__(256, 2) void out_mma(float* __restrict__ out)
{
    extern __shared__ u32 sm[];
    u32* sAh = sm;
    u32* sAl = sAh + 128 * 36;
    u32* sBh = sAl + 128 * 36;
    u32* sBl = sBh + 128 * 36;

    const int n0 = blockIdx.x * 128;
    const int m0 = blockIdx.y * 128;

    float c[16][4] = {};
    gemm_core((const uint4*)g_avh + (size_t)m0 * 64,
              (const uint4*)g_avl + (size_t)m0 * 64,
              (const uint4*)(g_wh + (size_t)3 * WSZ) + (size_t)n0 * 64,
              (const uint4*)(g_wl + (size_t)3 * WSZ) + (size_t)n0 * 64,
              sAh, sAl, sBh, sBl, c);

    const int tid = threadIdx.x, w = tid >> 5, lane = tid & 31;
    const int lr = lane >> 2, lc = lane & 3;
    #pragma unroll
    for (int t = 0; t < 16; t++) {
        int col = n0 + 8 * t + 2 * lc;
        #pragma unroll
        for (int half = 0; half < 2; half++) {
            int m = m0 + 16 * w + lr + 8 * half;
            *(float2*)&out[(size_t)m * DIM + col] =
                make_float2(c[t][2 * half], c[t][2 * half + 1]);
        }
    }
}

// ---------------------------------------------------------------------------
extern "C" void kernel_launch(void* const* d_in, const int* in_sizes, int n_in,
                              void* d_out, int out_size)
{
    const float* query = (const float*)d_in[0];
    const float* key   = (const float*)d_in[1];
    const float* value = (const float*)d_in[2];
    const float* Wq    = (const float*)d_in[3];
    const float* Wk    = (const float*)d_in[4];
    const float* Wv    = (const float*)d_in[5];
    const float* Wo    = (const float*)d_in[6];
    const int*   amask = (const int*)d_in[7];
    float*       out   = (float*)d_out;

    (void)in_sizes; (void)n_in; (void)out_size;

    split_kernel<<<dim3(2048, 7), 256>>>(query, key, value, Wq, Wk, Wv, Wo);

    cudaFuncSetAttribute(proj_mma, cudaFuncAttributeMaxDynamicSharedMemorySize, GEMM_SMEM);
    proj_mma<<<dim3(4, 64, 3), 256, GEMM_SMEM>>>();

    cudaFuncSetAttribute(attn_kernel, cudaFuncAttributeMaxDynamicSharedMemorySize, ATTN_SMEM);
    attn_kernel<<<dim3(SEQ / 128, NH, Bz), 256, ATTN_SMEM>>>(amask);

    cudaFuncSetAttribute(out_mma, cudaFuncAttributeMaxDynamicSharedMemorySize, GEMM_SMEM);
    out_mma<<<dim3(4, 64), 256, GEMM_SMEM>>>(out);
}

// round 14
// speedup vs baseline: 2.4972x; 1.0344x over previous
#include <cuda_runtime.h>
#include <cuda_bf16.h>

#define Bz   4
#define SEQ  2048
#define DIM  512
#define NH   8
#define HDIM 64

typedef unsigned int u32;

#define XSZ (8192 * 256)   // u32 pairs per X tensor
#define WSZ (512 * 256)    // u32 pairs per W tensor

// ---- bf16 helpers -----------------------------------------------------------
__device__ __forceinline__ u32 bfpack(float x, float y) {   // lo half = x
    u32 r; asm("cvt.rn.bf16x2.f32 %0, %1, %2;" : "=r"(r) : "f"(y), "f"(x)); return r;
}
__device__ __forceinline__ float bfround(float x) {
    return __bfloat162float(__float2bfloat16_rn(x));
}
__device__ __forceinline__ void split2(float x, float y, u32& h, u32& l) {
    float hx = bfround(x), hy = bfround(y);
    h = bfpack(hx, hy);
    l = bfpack(x - hx, y - hy);
}

// ---- mma / ldmatrix / cp.async ----------------------------------------------
__device__ __forceinline__ void mma_bf16(float* d, const u32* a, const u32* b) {
    asm("mma.sync.aligned.m16n8k16.row.col.f32.bf16.bf16.f32 "
        "{%0,%1,%2,%3}, {%4,%5,%6,%7}, {%8,%9}, {%0,%1,%2,%3};"
        : "+f"(d[0]), "+f"(d[1]), "+f"(d[2]), "+f"(d[3])
        : "r"(a[0]), "r"(a[1]), "r"(a[2]), "r"(a[3]), "r"(b[0]), "r"(b[1]));
}
__device__ __forceinline__ u32 sptr(const void* p) {
    return (u32)__cvta_generic_to_shared(p);
}
__device__ __forceinline__ void ldsm4(u32 a, u32& r0, u32& r1, u32& r2, u32& r3) {
    asm volatile("ldmatrix.sync.aligned.m8n8.x4.shared.b16 {%0,%1,%2,%3}, [%4];"
                 : "=r"(r0), "=r"(r1), "=r"(r2), "=r"(r3) : "r"(a));
}
__device__ __forceinline__ void cpasync16(u32 s, const void* g) {
    asm volatile("cp.async.ca.shared.global [%0], [%1], 16;" :: "r"(s), "l"(g));
}

// ---- device-global scratch ---------------------------------------------------
__device__ u32 g_xh[(size_t)3 * XSZ], g_xl[(size_t)3 * XSZ];
__device__ u32 g_wh[(size_t)4 * WSZ], g_wl[(size_t)4 * WSZ];
__device__ u32 g_qh[(size_t)Bz * NH * SEQ * 32];
__device__ u32 g_ql[(size_t)Bz * NH * SEQ * 32];
__device__ u32 g_kh[(size_t)Bz * NH * SEQ * 32];
__device__ u32 g_kl[(size_t)Bz * NH * SEQ * 32];
__device__ u32 g_vh[(size_t)Bz * NH * HDIM * 1024];
__device__ u32 g_vl[(size_t)Bz * NH * HDIM * 1024];
__device__ u32 g_avh[(size_t)8192 * 256];
__device__ u32 g_avl[(size_t)8192 * 256];

// ---------------------------------------------------------------------------
// Split pre-pass.
// ---------------------------------------------------------------------------
__global__ __launch_bounds__(256) void split_kernel(
    const float* __restrict__ Xq, const float* __restrict__ Xk,
    const float* __restrict__ Xv, const float* __restrict__ Wq,
    const float* __restrict__ Wk, const float* __restrict__ Wv,
    const float* __restrict__ Wo)
{
    const int z = blockIdx.y;
    const float* src; u32 *dh, *dl; int n8;
    if (z < 3) {
        src = (z == 0) ? Xq : (z == 1) ? Xk : Xv;
        dh = g_xh + (size_t)z * XSZ; dl = g_xl + (size_t)z * XSZ;
        n8 = (8192 * 512) / 8;
    } else {
        int i = z - 3;
        src = (i == 0) ? Wq : (i == 1) ? Wk : (i == 2) ? Wv : Wo;
        dh = g_wh + (size_t)i * WSZ; dl = g_wl + (size_t)i * WSZ;
        n8 = (512 * 512) / 8;
    }
    int g = blockIdx.x * 256 + threadIdx.x;
    if (g >= n8) return;
    const float4* s4 = (const float4*)src;
    float4 f0 = s4[2 * g], f1 = s4[2 * g + 1];
    uint4 H, L;
    split2(f0.x, f0.y, H.x, L.x);
    split2(f0.z, f0.w, H.y, L.y);
    split2(f1.x, f1.y, H.z, L.z);
    split2(f1.z, f1.w, H.w, L.w);
    ((uint4*)dh)[g] = H;
    ((uint4*)dl)[g] = L;
}

// ---------------------------------------------------------------------------
// GEMM core v2: C[128,128] = A @ B^T over k=512, 3-way split mma,
// ldmatrix fragments + cp.async 2-stage double buffering.
// smem: 2 stages x {Ah, Al, Bh, Bl} each [128][36] u32.
// ---------------------------------------------------------------------------
#define ARR_B  (128 * 36 * 4)              // bytes per array
#define STG_B  (4 * ARR_B)                 // bytes per stage
#define GEMM_SMEM (2 * STG_B)              // 147,456 B

__device__ __forceinline__ void gemm_load_stage(
    u32 sb, const uint4* __restrict__ A4h, const uint4* __restrict__ A4l,
    const uint4* __restrict__ B4h, const uint4* __restrict__ B4l, int kt, int tid)
{
    #pragma unroll
    for (int it = 0; it < 4; it++) {
        int e = tid + it * 256;
        int row = e >> 3, c4 = e & 7;
        u32 so = sb + (u32)(row * 36 + 4 * c4) * 4;
        size_t go = (size_t)row * 64 + kt * 8 + c4;
        cpasync16(so,             &A4h[go]);
        cpasync16(so + ARR_B,     &A4l[go]);
        cpasync16(so + 2 * ARR_B, &B4h[go]);
        cpasync16(so + 3 * ARR_B, &B4l[go]);
    }
    asm volatile("cp.async.commit_group;");
}

__device__ __forceinline__ void gemm_core(
    const uint4* __restrict__ A4h, const uint4* __restrict__ A4l,
    const uint4* __restrict__ B4h, const uint4* __restrict__ B4l,
    u32* smem, float c[16][4])
{
    const int tid  = threadIdx.x;
    const int w    = tid >> 5;
    const int lane = tid & 31;

    // ldmatrix lane addressing (validated fragment<->matrix mapping)
    const int arow = 16 * w + (lane & 7) + 8 * ((lane >> 3) & 1);
    const int acol = 4 * (lane >> 4);
    const int brow = (lane & 7) + 8 * (lane >> 4);
    const int bcol = 4 * ((lane >> 3) & 1);

    const u32 base = sptr(smem);

    gemm_load_stage(base, A4h, A4l, B4h, B4l, 0, tid);

    for (int kt = 0; kt < 8; kt++) {
        const u32 sb = base + (u32)(kt & 1) * STG_B;
        if (kt + 1 < 8) {
            gemm_load_stage(base + (u32)((kt + 1) & 1) * STG_B,
                            A4h, A4l, B4h, B4l, kt + 1, tid);
            asm volatile("cp.async.wait_group 1;");
        } else {
            asm volatile("cp.async.wait_group 0;");
        }
        __syncthreads();

        const u32 aHb = sb + (u32)(arow * 36 + acol) * 4;
        const u32 bHb = sb + 2 * ARR_B + (u32)(brow * 36 + bcol) * 4;
        #pragma unroll
        for (int ch = 0; ch < 4; ch++) {
            u32 aH[4], aL[4];
            ldsm4(aHb + 32 * ch,         aH[0], aH[1], aH[2], aH[3]);
            ldsm4(aHb + ARR_B + 32 * ch, aL[0], aL[1], aL[2], aL[3]);
            #pragma unroll
            for (int tp = 0; tp < 8; tp++) {
                u32 h0, h1, h2, h3, l0, l1, l2, l3;
                u32 off = 32 * ch + (u32)tp * (16 * 36 * 4);
                ldsm4(bHb + off,         h0, h1, h2, h3);
                ldsm4(bHb + ARR_B + off, l0, l1, l2, l3);
                u32 bh0[2] = {h0, h1}, bh1[2] = {h2, h3};
                u32 bl0[2] = {l0, l1}, bl1[2] = {l2, l3};
                mma_bf16(c[2 * tp],     aH, bh0);
                mma_bf16(c[2 * tp],     aH, bl0);
                mma_bf16(c[2 * tp],     aL, bh0);
                mma_bf16(c[2 * tp + 1], aH, bh1);
                mma_bf16(c[2 * tp + 1], aH, bl1);
                mma_bf16(c[2 * tp + 1], aL, bh1);
            }
        }
        __syncthreads();
    }
}

// ---------------------------------------------------------------------------
// Projections (epilogues unchanged from R13).
// ---------------------------------------------------------------------------
__global__ __launch_bounds__(256, 1) void proj_mma()
{
    extern __shared__ u32 sm[];

    const int z = blockIdx.z;
    int m0, n0;
    const u32 *Ah, *Al, *Bh, *Bl;
    if (z < 2) {
        m0 = blockIdx.y * 128; n0 = blockIdx.x * 128;
        Ah = g_xh + (size_t)z * XSZ; Al = g_xl + (size_t)z * XSZ;
        Bh = g_wh + (size_t)z * WSZ; Bl = g_wl + (size_t)z * WSZ;
    } else {
        m0 = blockIdx.x * 128; n0 = blockIdx.y * 128;
        Ah = g_wh + (size_t)2 * WSZ; Al = g_wl + (size_t)2 * WSZ;
        Bh = g_xh + (size_t)2 * XSZ; Bl = g_xl + (size_t)2 * XSZ;
    }

    float c[16][4] = {};
    gemm_core((const uint4*)Ah + (size_t)m0 * 64, (const uint4*)Al + (size_t)m0 * 64,
              (const uint4*)Bh + (size_t)n0 * 64, (const uint4*)Bl + (size_t)n0 * 64,
              sm, c);

    const int tid = threadIdx.x, w = tid >> 5, lane = tid & 31;
    const int lr = lane >> 2, lc = lane & 3;

    if (z < 2) {
        u32* oh = z ? g_kh : g_qh;
        u32* ol = z ? g_kl : g_ql;
        const float sc = z ? 1.0f : 0.125f;
        #pragma unroll
        for (int t = 0; t < 16; t++) {
            int ng = n0 + 8 * t + 2 * lc;
            int h = ng >> 6, pidx = (ng & 63) >> 1;
            #pragma unroll
            for (int half = 0; half < 2; half++) {
                int m = m0 + 16 * w + lr + 8 * half;
                int b = m >> 11, l = m & 2047;
                size_t base = ((size_t)(b * NH + h) * SEQ + l) * 32 + pidx;
                u32 H, L;
                split2(c[t][2 * half] * sc, c[t][2 * half + 1] * sc, H, L);
                oh[base] = H; ol[base] = L;
            }
        }
    } else {
        #pragma unroll
        for (int t = 0; t < 16; t++) {
            int kg = n0 + 8 * t + 2 * lc;
            int b = kg >> 11, l = kg & 2047;
            #pragma unroll
            for (int half = 0; half < 2; half++) {
                int dg = m0 + 16 * w + lr + 8 * half;
                int h = dg >> 6, hd = dg & 63;
                size_t base = ((size_t)(b * NH + h) * HDIM + hd) * 1024 + (l >> 1);
                u32 H, L;
                split2(c[t][2 * half], c[t][2 * half + 1], H, L);
                g_vh[base] = H; g_vl[base] = L;
            }
        }
    }
}

// ---------------------------------------------------------------------------
// Tensor-core attention with ldmatrix fragment loads.
// ---------------------------------------------------------------------------
#define QROW 36
#define ATTN_SMEM ((2 * 128 * QROW + 4 * 64 * QROW + 64) * 4)   // 73,984 B

__global__ __launch_bounds__(256, 2) void attn_kernel(const int* __restrict__ amask)
{
    extern __shared__ u32 smu[];
    u32* qh = smu;
    u32* ql = qh + 128 * QROW;
    u32* kh = ql + 128 * QROW;
    u32* kl = kh + 64 * QROW;
    u32* vh = kl + 64 * QROW;
    u32* vl = vh + 64 * QROW;
    int* m_s = (int*)(vl + 64 * QROW);

    const int q0   = blockIdx.x * 128;
    const int h    = blockIdx.y;
    const int b    = blockIdx.z;
    const int tid  = threadIdx.x;
    const int w    = tid >> 5;
    const int lane = tid & 31;
    const int lr   = lane >> 2, lc = lane & 3;

    const int arow = 16 * w + (lane & 7) + 8 * ((lane >> 3) & 1);
    const int acol = 4 * (lane >> 4);
    const int brow = (lane & 7) + 8 * (lane >> 4);
    const int bcol = 4 * ((lane >> 3) & 1);

    const u32 qHb = sptr(qh) + (u32)(arow * QROW + acol) * 4;
    const u32 qLb = sptr(ql) + (u32)(arow * QROW + acol) * 4;
    const u32 kHb = sptr(kh) + (u32)(brow * QROW + bcol) * 4;
    const u32 kLb = sptr(kl) + (u32)(brow * QROW + bcol) * 4;
    const u32 vHb = sptr(vh) + (u32)(brow * QROW + bcol) * 4;
    const u32 vLb = sptr(vl) + (u32)(brow * QROW + bcol) * 4;

    const size_t bh  = (size_t)(b * NH + h);
    const size_t qb4 = (bh * SEQ + q0) * 8;
    const size_t kb4 = (bh * SEQ) * 8;
    const size_t vb4 = (bh * HDIM) * 256;

    #pragma unroll
    for (int it = 0; it < 4; it++) {
        int e = tid + it * 256;
        int row = e >> 3, c4 = e & 7;
        *(uint4*)&qh[row * QROW + 4 * c4] = ((const uint4*)g_qh)[qb4 + e];
        *(uint4*)&ql[row * QROW + 4 * c4] = ((const uint4*)g_ql)[qb4 + e];
    }

    float o[8][4] = {};
    float lrow0 = 0.f, lrow1 = 0.f;

    for (int kt = 0; kt < SEQ / 64; kt++) {
        __syncthreads();
        #pragma unroll
        for (int it = 0; it < 2; it++) {
            int e = tid + it * 256;
            int row = e >> 3, c4 = e & 7;
            *(uint4*)&kh[row * QROW + 4 * c4] = ((const uint4*)g_kh)[kb4 + kt * 512 + e];
            *(uint4*)&kl[row * QROW + 4 * c4] = ((const uint4*)g_kl)[kb4 + kt * 512 + e];
            *(uint4*)&vh[row * QROW + 4 * c4] = ((const uint4*)g_vh)[vb4 + row * 256 + kt * 8 + c4];
            *(uint4*)&vl[row * QROW + 4 * c4] = ((const uint4*)g_vl)[vb4 + row * 256 + kt * 8 + c4];
        }
        if (tid < 64) m_s[tid] = amask[b * SEQ + kt * 64 + tid];
        __syncthreads();

        // ---- S = Q K^T ----
        float s[8][4] = {};
        #pragma unroll
        for (int ch = 0; ch < 4; ch++) {
            u32 aH[4], aL[4];
            ldsm4(qHb + 32 * ch, aH[0], aH[1], aH[2], aH[3]);
            ldsm4(qLb + 32 * ch, aL[0], aL[1], aL[2], aL[3]);
            #pragma unroll
            for (int tp = 0; tp < 4; tp++) {
                u32 h0, h1, h2, h3, l0, l1, l2, l3;
                u32 off = 32 * ch + (u32)tp * (16 * QROW * 4);
                ldsm4(kHb + off, h0, h1, h2, h3);
                ldsm4(kLb + off, l0, l1, l2, l3);
                u32 bh0[2] = {h0, h1}, bh1[2] = {h2, h3};
                u32 bl0[2] = {l0, l1}, bl1[2] = {l2, l3};
                mma_bf16(s[2 * tp],     aH, bh0);
                mma_bf16(s[2 * tp],     aH, bl0);
                mma_bf16(s[2 * tp],     aL, bh0);
                mma_bf16(s[2 * tp + 1], aH, bh1);
                mma_bf16(s[2 * tp + 1], aH, bl1);
                mma_bf16(s[2 * tp + 1], aL, bh1);
            }
        }

        // ---- exp + mask + row sums + register P split ----
        u32 pH0[8], pH1[8], pL0[8], pL1[8];
        #pragma unroll
        for (int t = 0; t < 8; t++) {
            int c0 = 8 * t + 2 * lc;
            bool d0 = (m_s[c0] == 0), d1 = (m_s[c0 + 1] == 0);
            float p0 = d0 ? 0.f : __expf(s[t][0]);
            float p1 = d1 ? 0.f : __expf(s[t][1]);
            float p2 = d0 ? 0.f : __expf(s[t][2]);
            float p3 = d1 ? 0.f : __expf(s[t][3]);
            lrow0 += p0 + p1;
            lrow1 += p2 + p3;
            float h0 = bfround(p0), h1 = bfround(p1);
            float h2 = bfround(p2), h3 = bfround(p3);
            pH0[t] = bfpack(h0, h1);           pH1[t] = bfpack(h2, h3);
            pL0[t] = bfpack(p0 - h0, p1 - h1); pL1[t] = bfpack(p2 - h2, p3 - h3);
        }

        // ---- O += P V ----
        #pragma unroll
        for (int ch = 0; ch < 4; ch++) {
            u32 aH[4] = { pH0[2 * ch], pH1[2 * ch], pH0[2 * ch + 1], pH1[2 * ch + 1] };
            u32 aL[4] = { pL0[2 * ch], pL1[2 * ch], pL0[2 * ch + 1], pL1[2 * ch + 1] };
            #pragma unroll
            for (int tp = 0; tp < 4; tp++) {
                u32 h0, h1, h2, h3, l0, l1, l2, l3;
                u32 off = 32 * ch + (u32)tp * (16 * QROW * 4);
                ldsm4(vHb + off, h0, h1, h2, h3);
                ldsm4(vLb + off, l0, l1, l2, l3);
                u32 bh0[2] = {h0, h1}, bh1[2] = {h2, h3};
                u32 bl0[2] = {l0, l1}, bl1[2] = {l2, l3};
                mma_bf16(o[2 * tp],     aH, bh0);
                mma_bf16(o[2 * tp],     aH, bl0);
                mma_bf16(o[2 * tp],     aL, bh0);
                mma_bf16(o[2 * tp + 1], aH, bh1);
                mma_bf16(o[2 * tp + 1], aH, bl1);
                mma_bf16(o[2 * tp + 1], aL, bh1);
            }
        }
    }

    lrow0 += __shfl_xor_sync(0xffffffffu, lrow0, 1);
    lrow0 += __shfl_xor_sync(0xffffffffu, lrow0, 2);
    lrow1 += __shfl_xor_sync(0xffffffffu, lrow1, 1);
    lrow1 += __shfl_xor_sync(0xffffffffu, lrow1, 2);
    float inv0 = 1.f / lrow0, inv1 = 1.f / lrow1;

    const int r0 = 16 * w + lr;
    const size_t a0 = (size_t)(b * SEQ + q0 + r0) * 256 + h * 32;
    const size_t a1 = (size_t)(b * SEQ + q0 + r0 + 8) * 256 + h * 32;
    #pragma unroll
    for (int t = 0; t < 8; t++) {
        u32 H, L;
        split2(o[t][0] * inv0, o[t][1] * inv0, H, L);
        g_avh[a0 + 4 * t + lc] = H; g_avl[a0 + 4 * t + lc] = L;
        split2(o[t][2] * inv1, o[t][3] * inv1, H, L);
        g_avh[a1 + 4 * t + lc] = H; g_avl[a1 + 4 * t + lc] = L;
    }
}

// ---------------------------------------------------------------------------
// Output projection.
// ---------------------------------------------------------------------------
__global__ __launch_bounds__(256, 1) void out_mma(float* __restrict__ out)
{
    extern __shared__ u32 sm[];

    const int n0 = blockIdx.x * 128;
    const int m0 = blockIdx.y * 128;

    float c[16][4] = {};
    gemm_core((const uint4*)g_avh + (size_t)m0 * 64,
              (const uint4*)g_avl + (size_t)m0 * 64,
              (const uint4*)(g_wh + (size_t)3 * WSZ) + (size_t)n0 * 64,
              (const uint4*)(g_wl + (size_t)3 * WSZ) + (size_t)n0 * 64,
              sm, c);

    const int tid = threadIdx.x, w = tid >> 5, lane = tid & 31;
    const int lr = lane >> 2, lc = lane & 3;
    #pragma unroll
    for (int t = 0; t < 16; t++) {
        int col = n0 + 8 * t + 2 * lc;
        #pragma unroll
        for (int half = 0; half < 2; half++) {
            int m = m0 + 16 * w + lr + 8 * half;
            *(float2*)&out[(size_t)m * DIM + col] =
                make_float2(c[t][2 * half], c[t][2 * half + 1]);
        }
    }
}

// ---------------------------------------------------------------------------
extern "C" void kernel_launch(void* const* d_in, const int* in_sizes, int n_in,
                              void* d_out, int out_size)
{
    const float* query = (const float*)d_in[0];
    const float* key   = (const float*)d_in[1];
    const float* value = (const float*)d_in[2];
    const float* Wq    = (const float*)d_in[3];
    const float* Wk    = (const float*)d_in[4];
    const float* Wv    = (const float*)d_in[5];
    const float* Wo    = (const float*)d_in[6];
    const int*   amask = (const int*)d_in[7];
    float*       out   = (float*)d_out;

    (void)in_sizes; (void)n_in; (void)out_size;

    split_kernel<<<dim3(2048, 7), 256>>>(query, key, value, Wq, Wk, Wv, Wo);

    cudaFuncSetAttribute(proj_mma, cudaFuncAttributeMaxDynamicSharedMemorySize, GEMM_SMEM);
    proj_mma<<<dim3(4, 64, 3), 256, GEMM_SMEM>>>();

    cudaFuncSetAttribute(attn_kernel, cudaFuncAttributeMaxDynamicSharedMemorySize, ATTN_SMEM);
    attn_kernel<<<dim3(SEQ / 128, NH, Bz), 256, ATTN_SMEM>>>(amask);

    cudaFuncSetAttribute(out_mma, cudaFuncAttributeMaxDynamicSharedMemorySize, GEMM_SMEM);
    out_mma<<<dim3(4, 64), 256, GEMM_SMEM>>>(out);
}

// round 16
// speedup vs baseline: 2.5181x; 1.0084x over previous
#include <cuda_runtime.h>
#include <cuda_bf16.h>

#define Bz   4
#define SEQ  2048
#define DIM  512
#define NH   8
#define HDIM 64

typedef unsigned int u32;

#define XSZ (8192 * 256)   // u32 pairs per X tensor
#define WSZ (512 * 256)    // u32 pairs per W tensor

// ---- bf16 helpers -----------------------------------------------------------
__device__ __forceinline__ u32 bfpack(float x, float y) {   // lo half = x
    u32 r; asm("cvt.rn.bf16x2.f32 %0, %1, %2;" : "=r"(r) : "f"(y), "f"(x)); return r;
}
__device__ __forceinline__ float bfround(float x) {
    return __bfloat162float(__float2bfloat16_rn(x));
}
__device__ __forceinline__ void split2(float x, float y, u32& h, u32& l) {
    float hx = bfround(x), hy = bfround(y);
    h = bfpack(hx, hy);
    l = bfpack(x - hx, y - hy);
}

// ---- mma / ldmatrix / cp.async ----------------------------------------------
__device__ __forceinline__ void mma_bf16(float* d, const u32* a, const u32* b) {
    asm("mma.sync.aligned.m16n8k16.row.col.f32.bf16.bf16.f32 "
        "{%0,%1,%2,%3}, {%4,%5,%6,%7}, {%8,%9}, {%0,%1,%2,%3};"
        : "+f"(d[0]), "+f"(d[1]), "+f"(d[2]), "+f"(d[3])
        : "r"(a[0]), "r"(a[1]), "r"(a[2]), "r"(a[3]), "r"(b[0]), "r"(b[1]));
}
__device__ __forceinline__ u32 sptr(const void* p) {
    return (u32)__cvta_generic_to_shared(p);
}
__device__ __forceinline__ void ldsm4(u32 a, u32* r) {
    asm volatile("ldmatrix.sync.aligned.m8n8.x4.shared.b16 {%0,%1,%2,%3}, [%4];"
                 : "=r"(r[0]), "=r"(r[1]), "=r"(r[2]), "=r"(r[3]) : "r"(a));
}
__device__ __forceinline__ void cpasync16(u32 s, const void* g) {
    asm volatile("cp.async.ca.shared.global [%0], [%1], 16;" :: "r"(s), "l"(g));
}

// ---- device-global scratch ---------------------------------------------------
__device__ u32 g_xh[(size_t)3 * XSZ], g_xl[(size_t)3 * XSZ];
__device__ u32 g_wh[(size_t)4 * WSZ], g_wl[(size_t)4 * WSZ];
__device__ u32 g_qh[(size_t)Bz * NH * SEQ * 32];
__device__ u32 g_ql[(size_t)Bz * NH * SEQ * 32];
__device__ u32 g_kh[(size_t)Bz * NH * SEQ * 32];
__device__ u32 g_kl[(size_t)Bz * NH * SEQ * 32];
__device__ u32 g_vh[(size_t)Bz * NH * HDIM * 1024];
__device__ u32 g_vl[(size_t)Bz * NH * HDIM * 1024];
__device__ u32 g_avh[(size_t)8192 * 256];
__device__ u32 g_avl[(size_t)8192 * 256];

// ---------------------------------------------------------------------------
// Split pre-pass.
// ---------------------------------------------------------------------------
__global__ __launch_bounds__(256) void split_kernel(
    const float* __restrict__ Xq, const float* __restrict__ Xk,
    const float* __restrict__ Xv, const float* __restrict__ Wq,
    const float* __restrict__ Wk, const float* __restrict__ Wv,
    const float* __restrict__ Wo)
{
    const int z = blockIdx.y;
    const float* src; u32 *dh, *dl; int n8;
    if (z < 3) {
        src = (z == 0) ? Xq : (z == 1) ? Xk : Xv;
        dh = g_xh + (size_t)z * XSZ; dl = g_xl + (size_t)z * XSZ;
        n8 = (8192 * 512) / 8;
    } else {
        int i = z - 3;
        src = (i == 0) ? Wq : (i == 1) ? Wk : (i == 2) ? Wv : Wo;
        dh = g_wh + (size_t)i * WSZ; dl = g_wl + (size_t)i * WSZ;
        n8 = (512 * 512) / 8;
    }
    int g = blockIdx.x * 256 + threadIdx.x;
    if (g >= n8) return;
    const float4* s4 = (const float4*)src;
    float4 f0 = s4[2 * g], f1 = s4[2 * g + 1];
    uint4 H, L;
    split2(f0.x, f0.y, H.x, L.x);
    split2(f0.z, f0.w, H.y, L.y);
    split2(f1.x, f1.y, H.z, L.z);
    split2(f1.z, f1.w, H.w, L.w);
    ((uint4*)dh)[g] = H;
    ((uint4*)dl)[g] = L;
}

// ---------------------------------------------------------------------------
// GEMM core: C[128,128] = A @ B^T over k=512, 3-way split mma,
// ldmatrix + cp.async double buffering. MMA issue is PASS-MAJOR over groups
// of 4 n-tiles so same-accumulator reuse distance is 8 MMAs (RAW hiding).
// ---------------------------------------------------------------------------
#define ARR_B  (128 * 36 * 4)              // bytes per array
#define STG_B  (4 * ARR_B)                 // bytes per stage
#define GEMM_SMEM (2 * STG_B)              // 147,456 B

__device__ __forceinline__ void gemm_load_stage(
    u32 sb, const uint4* __restrict__ A4h, const uint4* __restrict__ A4l,
    const uint4* __restrict__ B4h, const uint4* __restrict__ B4l, int kt, int tid)
{
    #pragma unroll
    for (int it = 0; it < 4; it++) {
        int e = tid + it * 256;
        int row = e >> 3, c4 = e & 7;
        u32 so = sb + (u32)(row * 36 + 4 * c4) * 4;
        size_t go = (size_t)row * 64 + kt * 8 + c4;
        cpasync16(so,             &A4h[go]);
        cpasync16(so + ARR_B,     &A4l[go]);
        cpasync16(so + 2 * ARR_B, &B4h[go]);
        cpasync16(so + 3 * ARR_B, &B4l[go]);
    }
    asm volatile("cp.async.commit_group;");
}

__device__ __forceinline__ void gemm_core(
    const uint4* __restrict__ A4h, const uint4* __restrict__ A4l,
    const uint4* __restrict__ B4h, const uint4* __restrict__ B4l,
    u32* smem, float c[16][4])
{
    const int tid  = threadIdx.x;
    const int w    = tid >> 5;
    const int lane = tid & 31;

    const int arow = 16 * w + (lane & 7) + 8 * ((lane >> 3) & 1);
    const int acol = 4 * (lane >> 4);
    const int brow = (lane & 7) + 8 * (lane >> 4);
    const int bcol = 4 * ((lane >> 3) & 1);

    const u32 base = sptr(smem);

    gemm_load_stage(base, A4h, A4l, B4h, B4l, 0, tid);

    for (int kt = 0; kt < 8; kt++) {
        const u32 sb = base + (u32)(kt & 1) * STG_B;
        if (kt + 1 < 8) {
            gemm_load_stage(base + (u32)((kt + 1) & 1) * STG_B,
                            A4h, A4l, B4h, B4l, kt + 1, tid);
            asm volatile("cp.async.wait_group 1;");
        } else {
            asm volatile("cp.async.wait_group 0;");
        }
        __syncthreads();

        const u32 aHb = sb + (u32)(arow * 36 + acol) * 4;
        const u32 bHb = sb + 2 * ARR_B + (u32)(brow * 36 + bcol) * 4;
        #pragma unroll
        for (int ch = 0; ch < 4; ch++) {
            u32 aH[4], aL[4];
            ldsm4(aHb + 32 * ch,         aH);
            ldsm4(aHb + ARR_B + 32 * ch, aL);
            #pragma unroll
            for (int half = 0; half < 2; half++) {
                u32 bH[4][4], bL[4][4];
                #pragma unroll
                for (int j = 0; j < 4; j++) {
                    u32 off = 32 * ch + (u32)(4 * half + j) * (16 * 36 * 4);
                    ldsm4(bHb + off,         bH[j]);
                    ldsm4(bHb + ARR_B + off, bL[j]);
                }
                // pass-major: same accumulator revisited every 8 MMAs
                #pragma unroll
                for (int j = 0; j < 4; j++) {
                    int tp = 4 * half + j;
                    mma_bf16(c[2 * tp],     aH, bH[j]);
                    mma_bf16(c[2 * tp + 1], aH, bH[j] + 2);
                }
                #pragma unroll
                for (int j = 0; j < 4; j++) {
                    int tp = 4 * half + j;
                    mma_bf16(c[2 * tp],     aH, bL[j]);
                    mma_bf16(c[2 * tp + 1], aH, bL[j] + 2);
                }
                #pragma unroll
                for (int j = 0; j < 4; j++) {
                    int tp = 4 * half + j;
                    mma_bf16(c[2 * tp],     aL, bH[j]);
                    mma_bf16(c[2 * tp + 1], aL, bH[j] + 2);
                }
            }
        }
        __syncthreads();
    }
}

// ---------------------------------------------------------------------------
// Projections.
// ---------------------------------------------------------------------------
__global__ __launch_bounds__(256, 1) void proj_mma()
{
    extern __shared__ u32 sm[];

    const int z = blockIdx.z;
    int m0, n0;
    const u32 *Ah, *Al, *Bh, *Bl;
    if (z < 2) {
        m0 = blockIdx.y * 128; n0 = blockIdx.x * 128;
        Ah = g_xh + (size_t)z * XSZ; Al = g_xl + (size_t)z * XSZ;
        Bh = g_wh + (size_t)z * WSZ; Bl = g_wl + (size_t)z * WSZ;
    } else {
        m0 = blockIdx.x * 128; n0 = blockIdx.y * 128;
        Ah = g_wh + (size_t)2 * WSZ; Al = g_wl + (size_t)2 * WSZ;
        Bh = g_xh + (size_t)2 * XSZ; Bl = g_xl + (size_t)2 * XSZ;
    }

    float c[16][4] = {};
    gemm_core((const uint4*)Ah + (size_t)m0 * 64, (const uint4*)Al + (size_t)m0 * 64,
              (const uint4*)Bh + (size_t)n0 * 64, (const uint4*)Bl + (size_t)n0 * 64,
              sm, c);

    const int tid = threadIdx.x, w = tid >> 5, lane = tid & 31;
    const int lr = lane >> 2, lc = lane & 3;

    if (z < 2) {
        u32* oh = z ? g_kh : g_qh;
        u32* ol = z ? g_kl : g_ql;
        const float sc = z ? 1.0f : 0.125f;
        #pragma unroll
        for (int t = 0; t < 16; t++) {
            int ng = n0 + 8 * t + 2 * lc;
            int h = ng >> 6, pidx = (ng & 63) >> 1;
            #pragma unroll
            for (int half = 0; half < 2; half++) {
                int m = m0 + 16 * w + lr + 8 * half;
                int b = m >> 11, l = m & 2047;
                size_t base = ((size_t)(b * NH + h) * SEQ + l) * 32 + pidx;
                u32 H, L;
                split2(c[t][2 * half] * sc, c[t][2 * half + 1] * sc, H, L);
                oh[base] = H; ol[base] = L;
            }
        }
    } else {
        #pragma unroll
        for (int t = 0; t < 16; t++) {
            int kg = n0 + 8 * t + 2 * lc;
            int b = kg >> 11, l = kg & 2047;
            #pragma unroll
            for (int half = 0; half < 2; half++) {
                int dg = m0 + 16 * w + lr + 8 * half;
                int h = dg >> 6, hd = dg & 63;
                size_t base = ((size_t)(b * NH + h) * HDIM + hd) * 1024 + (l >> 1);
                u32 H, L;
                split2(c[t][2 * half], c[t][2 * half + 1], H, L);
                g_vh[base] = H; g_vl[base] = L;
            }
        }
    }
}

// ---------------------------------------------------------------------------
// Attention: mma.sync + ldmatrix; MMA issue pass-major over pairs of n-tiles
// (reuse distance 4) to hide accumulator RAW without blowing the 2-CTA
// register budget.
// ---------------------------------------------------------------------------
#define QROW 36
#define ATTN_SMEM ((2 * 128 * QROW + 4 * 64 * QROW + 64) * 4)   // 73,984 B

__global__ __launch_bounds__(256, 2) void attn_kernel(const int* __restrict__ amask)
{
    extern __shared__ u32 smu[];
    u32* qh = smu;
    u32* ql = qh + 128 * QROW;
    u32* kh = ql + 128 * QROW;
    u32* kl = kh + 64 * QROW;
    u32* vh = kl + 64 * QROW;
    u32* vl = vh + 64 * QROW;
    int* m_s = (int*)(vl + 64 * QROW);

    const int q0   = blockIdx.x * 128;
    const int h    = blockIdx.y;
    const int b    = blockIdx.z;
    const int tid  = threadIdx.x;
    const int w    = tid >> 5;
    const int lane = tid & 31;
    const int lr   = lane >> 2, lc = lane & 3;

    const int arow = 16 * w + (lane & 7) + 8 * ((lane >> 3) & 1);
    const int acol = 4 * (lane >> 4);
    const int brow = (lane & 7) + 8 * (lane >> 4);
    const int bcol = 4 * ((lane >> 3) & 1);

    const u32 qHb = sptr(qh) + (u32)(arow * QROW + acol) * 4;
    const u32 qLb = sptr(ql) + (u32)(arow * QROW + acol) * 4;
    const u32 kHb = sptr(kh) + (u32)(brow * QROW + bcol) * 4;
    const u32 kLb = sptr(kl) + (u32)(brow * QROW + bcol) * 4;
    const u32 vHb = sptr(vh) + (u32)(brow * QROW + bcol) * 4;
    const u32 vLb = sptr(vl) + (u32)(brow * QROW + bcol) * 4;

    const size_t bh  = (size_t)(b * NH + h);
    const size_t qb4 = (bh * SEQ + q0) * 8;
    const size_t kb4 = (bh * SEQ) * 8;
    const size_t vb4 = (bh * HDIM) * 256;

    #pragma unroll
    for (int it = 0; it < 4; it++) {
        int e = tid + it * 256;
        int row = e >> 3, c4 = e & 7;
        *(uint4*)&qh[row * QROW + 4 * c4] = ((const uint4*)g_qh)[qb4 + e];
        *(uint4*)&ql[row * QROW + 4 * c4] = ((const uint4*)g_ql)[qb4 + e];
    }

    float o[8][4] = {};
    float lrow0 = 0.f, lrow1 = 0.f;

    for (int kt = 0; kt < SEQ / 64; kt++) {
        __syncthreads();
        #pragma unroll
        for (int it = 0; it < 2; it++) {
            int e = tid + it * 256;
            int row = e >> 3, c4 = e & 7;
            *(uint4*)&kh[row * QROW + 4 * c4] = ((const uint4*)g_kh)[kb4 + kt * 512 + e];
            *(uint4*)&kl[row * QROW + 4 * c4] = ((const uint4*)g_kl)[kb4 + kt * 512 + e];
            *(uint4*)&vh[row * QROW + 4 * c4] = ((const uint4*)g_vh)[vb4 + row * 256 + kt * 8 + c4];
            *(uint4*)&vl[row * QROW + 4 * c4] = ((const uint4*)g_vl)[vb4 + row * 256 + kt * 8 + c4];
        }
        if (tid < 64) m_s[tid] = amask[b * SEQ + kt * 64 + tid];
        __syncthreads();

        // ---- S = Q K^T (pass-major over pairs of n-tiles) ----
        float s[8][4] = {};
        #pragma unroll
        for (int ch = 0; ch < 4; ch++) {
            u32 aH[4], aL[4];
            ldsm4(qHb + 32 * ch, aH);
            ldsm4(qLb + 32 * ch, aL);
            #pragma unroll
            for (int half = 0; half < 2; half++) {
                u32 bH[2][4], bL[2][4];
                #pragma unroll
                for (int j = 0; j < 2; j++) {
                    u32 off = 32 * ch + (u32)(2 * half + j) * (16 * QROW * 4);
                    ldsm4(kHb + off, bH[j]);
                    ldsm4(kLb + off, bL[j]);
                }
                #pragma unroll
                for (int j = 0; j < 2; j++) {
                    int tp = 2 * half + j;
                    mma_bf16(s[2 * tp],     aH, bH[j]);
                    mma_bf16(s[2 * tp + 1], aH, bH[j] + 2);
                }
                #pragma unroll
                for (int j = 0; j < 2; j++) {
                    int tp = 2 * half + j;
                    mma_bf16(s[2 * tp],     aH, bL[j]);
                    mma_bf16(s[2 * tp + 1], aH, bL[j] + 2);
                }
                #pragma unroll
                for (int j = 0; j < 2; j++) {
                    int tp = 2 * half + j;
                    mma_bf16(s[2 * tp],     aL, bH[j]);
                    mma_bf16(s[2 * tp + 1], aL, bH[j] + 2);
                }
            }
        }

        // ---- exp + mask + row sums + register P split ----
        u32 pH0[8], pH1[8], pL0[8], pL1[8];
        #pragma unroll
        for (int t = 0; t < 8; t++) {
            int c0 = 8 * t + 2 * lc;
            bool d0 = (m_s[c0] == 0), d1 = (m_s[c0 + 1] == 0);
            float p0 = d0 ? 0.f : __expf(s[t][0]);
            float p1 = d1 ? 0.f : __expf(s[t][1]);
            float p2 = d0 ? 0.f : __expf(s[t][2]);
            float p3 = d1 ? 0.f : __expf(s[t][3]);
            lrow0 += p0 + p1;
            lrow1 += p2 + p3;
            float h0 = bfround(p0), h1 = bfround(p1);
            float h2 = bfround(p2), h3 = bfround(p3);
            pH0[t] = bfpack(h0, h1);           pH1[t] = bfpack(h2, h3);
            pL0[t] = bfpack(p0 - h0, p1 - h1); pL1[t] = bfpack(p2 - h2, p3 - h3);
        }

        // ---- O += P V (pass-major over pairs of n-tiles) ----
        #pragma unroll
        for (int ch = 0; ch < 4; ch++) {
            u32 aH[4] = { pH0[2 * ch], pH1[2 * ch], pH0[2 * ch + 1], pH1[2 * ch + 1] };
            u32 aL[4] = { pL0[2 * ch], pL1[2 * ch], pL0[2 * ch + 1], pL1[2 * ch + 1] };
            #pragma unroll
            for (int half = 0; half < 2; half++) {
                u32 bH[2][4], bL[2][4];
                #pragma unroll
                for (int j = 0; j < 2; j++) {
                    u32 off = 32 * ch + (u32)(2 * half + j) * (16 * QROW * 4);
                    ldsm4(vHb + off, bH[j]);
                    ldsm4(vLb + off, bL[j]);
                }
                #pragma unroll
                for (int j = 0; j < 2; j++) {
                    int tp = 2 * half + j;
                    mma_bf16(o[2 * tp],     aH, bH[j]);
                    mma_bf16(o[2 * tp + 1], aH, bH[j] + 2);
                }
                #pragma unroll
                for (int j = 0; j < 2; j++) {
                    int tp = 2 * half + j;
                    mma_bf16(o[2 * tp],     aH, bL[j]);
                    mma_bf16(o[2 * tp + 1], aH, bL[j] + 2);
                }
                #pragma unroll
                for (int j = 0; j < 2; j++) {
                    int tp = 2 * half + j;
                    mma_bf16(o[2 * tp],     aL, bH[j]);
                    mma_bf16(o[2 * tp + 1], aL, bH[j] + 2);
                }
            }
        }
    }

    lrow0 += __shfl_xor_sync(0xffffffffu, lrow0, 1);
    lrow0 += __shfl_xor_sync(0xffffffffu, lrow0, 2);
    lrow1 += __shfl_xor_sync(0xffffffffu, lrow1, 1);
    lrow1 += __shfl_xor_sync(0xffffffffu, lrow1, 2);
    float inv0 = 1.f / lrow0, inv1 = 1.f / lrow1;

    const int r0 = 16 * w + lr;
    const size_t a0 = (size_t)(b * SEQ + q0 + r0) * 256 + h * 32;
    const size_t a1 = (size_t)(b * SEQ + q0 + r0 + 8) * 256 + h * 32;
    #pragma unroll
    for (int t = 0; t < 8; t++) {
        u32 H, L;
        split2(o[t][0] * inv0, o[t][1] * inv0, H, L);
        g_avh[a0 + 4 * t + lc] = H; g_avl[a0 + 4 * t + lc] = L;
        split2(o[t][2] * inv1, o[t][3] * inv1, H, L);
        g_avh[a1 + 4 * t + lc] = H; g_avl[a1 + 4 * t + lc] = L;
    }
}

// ---------------------------------------------------------------------------
// Output projection.
// ---------------------------------------------------------------------------
__global__ __launch_bounds__(256, 1) void out_mma(float* __restrict__ out)
{
    extern __shared__ u32 sm[];

    const int n0 = blockIdx.x * 128;
    const int m0 = blockIdx.y * 128;

    float c[16][4] = {};
    gemm_core((const uint4*)g_avh + (size_t)m0 * 64,
              (const uint4*)g_avl + (size_t)m0 * 64,
              (const uint4*)(g_wh + (size_t)3 * WSZ) + (size_t)n0 * 64,
              (const uint4*)(g_wl + (size_t)3 * WSZ) + (size_t)n0 * 64,
              sm, c);

    const int tid = threadIdx.x, w = tid >> 5, lane = tid & 31;
    const int lr = lane >> 2, lc = lane & 3;
    #pragma unroll
    for (int t = 0; t < 16; t++) {
        int col = n0 + 8 * t + 2 * lc;
        #pragma unroll
        for (int half = 0; half < 2; half++) {
            int m = m0 + 16 * w + lr + 8 * half;
            *(float2*)&out[(size_t)m * DIM + col] =
                make_float2(c[t][2 * half], c[t][2 * half + 1]);
        }
    }
}

// ---------------------------------------------------------------------------
extern "C" void kernel_launch(void* const* d_in, const int* in_sizes, int n_in,
                              void* d_out, int out_size)
{
    const float* query = (const float*)d_in[0];
    const float* key   = (const float*)d_in[1];
    const float* value = (const float*)d_in[2];
    const float* Wq    = (const float*)d_in[3];
    const float* Wk    = (const float*)d_in[4];
    const float* Wv    = (const float*)d_in[5];
    const float* Wo    = (const float*)d_in[6];
    const int*   amask = (const int*)d_in[7];
    float*       out   = (float*)d_out;

    (void)in_sizes; (void)n_in; (void)out_size;

    split_kernel<<<dim3(2048, 7), 256>>>(query, key, value, Wq, Wk, Wv, Wo);

    cudaFuncSetAttribute(proj_mma, cudaFuncAttributeMaxDynamicSharedMemorySize, GEMM_SMEM);
    proj_mma<<<dim3(4, 64, 3), 256, GEMM_SMEM>>>();

    cudaFuncSetAttribute(attn_kernel, cudaFuncAttributeMaxDynamicSharedMemorySize, ATTN_SMEM);
    attn_kernel<<<dim3(SEQ / 128, NH, Bz), 256, ATTN_SMEM>>>(amask);

    cudaFuncSetAttribute(out_mma, cudaFuncAttributeMaxDynamicSharedMemorySize, GEMM_SMEM);
    out_mma<<<dim3(4, 64), 256, GEMM_SMEM>>>(out);
}

// round 17
// speedup vs baseline: 2.5869x; 1.0273x over previous
#include <cuda_runtime.h>
#include <cuda_bf16.h>

#define Bz   4
#define SEQ  2048
#define DIM  512
#define NH   8
#define HDIM 64

typedef unsigned int u32;

#define XSZ (8192 * 256)   // u32 pairs per X tensor
#define WSZ (512 * 256)    // u32 pairs per W tensor

// ---- bf16 helpers -----------------------------------------------------------
__device__ __forceinline__ u32 bfpack(float x, float y) {   // lo half = x
    u32 r; asm("cvt.rn.bf16x2.f32 %0, %1, %2;" : "=r"(r) : "f"(y), "f"(x)); return r;
}
__device__ __forceinline__ float bfround(float x) {
    return __bfloat162float(__float2bfloat16_rn(x));
}
__device__ __forceinline__ void split2(float x, float y, u32& h, u32& l) {
    float hx = bfround(x), hy = bfround(y);
    h = bfpack(hx, hy);
    l = bfpack(x - hx, y - hy);
}

// ---- mma / ldmatrix / cp.async ----------------------------------------------
__device__ __forceinline__ void mma_bf16(float* d, const u32* a, const u32* b) {
    asm("mma.sync.aligned.m16n8k16.row.col.f32.bf16.bf16.f32 "
        "{%0,%1,%2,%3}, {%4,%5,%6,%7}, {%8,%9}, {%0,%1,%2,%3};"
        : "+f"(d[0]), "+f"(d[1]), "+f"(d[2]), "+f"(d[3])
        : "r"(a[0]), "r"(a[1]), "r"(a[2]), "r"(a[3]), "r"(b[0]), "r"(b[1]));
}
__device__ __forceinline__ u32 sptr(const void* p) {
    return (u32)__cvta_generic_to_shared(p);
}
__device__ __forceinline__ void ldsm4(u32 a, u32* r) {
    asm volatile("ldmatrix.sync.aligned.m8n8.x4.shared.b16 {%0,%1,%2,%3}, [%4];"
                 : "=r"(r[0]), "=r"(r[1]), "=r"(r[2]), "=r"(r[3]) : "r"(a));
}
__device__ __forceinline__ void cpasync16(u32 s, const void* g) {
    asm volatile("cp.async.ca.shared.global [%0], [%1], 16;" :: "r"(s), "l"(g));
}

// ---- device-global scratch ---------------------------------------------------
__device__ u32 g_xh[(size_t)3 * XSZ], g_xl[(size_t)3 * XSZ];
__device__ u32 g_wh[(size_t)4 * WSZ], g_wl[(size_t)4 * WSZ];
__device__ u32 g_qh[(size_t)Bz * NH * SEQ * 32];
__device__ u32 g_ql[(size_t)Bz * NH * SEQ * 32];
__device__ u32 g_kh[(size_t)Bz * NH * SEQ * 32];
__device__ u32 g_kl[(size_t)Bz * NH * SEQ * 32];
__device__ u32 g_vh[(size_t)Bz * NH * HDIM * 1024];
__device__ u32 g_vl[(size_t)Bz * NH * HDIM * 1024];
__device__ u32 g_avh[(size_t)8192 * 256];
__device__ u32 g_avl[(size_t)8192 * 256];

// ---------------------------------------------------------------------------
// Split pre-pass.
// ---------------------------------------------------------------------------
__global__ __launch_bounds__(256) void split_kernel(
    const float* __restrict__ Xq, const float* __restrict__ Xk,
    const float* __restrict__ Xv, const float* __restrict__ Wq,
    const float* __restrict__ Wk, const float* __restrict__ Wv,
    const float* __restrict__ Wo)
{
    const int z = blockIdx.y;
    const float* src; u32 *dh, *dl; int n8;
    if (z < 3) {
        src = (z == 0) ? Xq : (z == 1) ? Xk : Xv;
        dh = g_xh + (size_t)z * XSZ; dl = g_xl + (size_t)z * XSZ;
        n8 = (8192 * 512) / 8;
    } else {
        int i = z - 3;
        src = (i == 0) ? Wq : (i == 1) ? Wk : (i == 2) ? Wv : Wo;
        dh = g_wh + (size_t)i * WSZ; dl = g_wl + (size_t)i * WSZ;
        n8 = (512 * 512) / 8;
    }
    int g = blockIdx.x * 256 + threadIdx.x;
    if (g >= n8) return;
    const float4* s4 = (const float4*)src;
    float4 f0 = s4[2 * g], f1 = s4[2 * g + 1];
    uint4 H, L;
    split2(f0.x, f0.y, H.x, L.x);
    split2(f0.z, f0.w, H.y, L.y);
    split2(f1.x, f1.y, H.z, L.z);
    split2(f1.z, f1.w, H.w, L.w);
    ((uint4*)dh)[g] = H;
    ((uint4*)dl)[g] = L;
}

// ---------------------------------------------------------------------------
// GEMM core: C[128,128] = A @ B^T over k=512, 3-way split mma.
// SINGLE-stage smem (73.7 KB) -> 2 CTAs/SM; cross-CTA overlap hides the
// load/barrier phases. Pass-major over pairs of n-tiles (reuse distance 4).
// ---------------------------------------------------------------------------
#define ARR_B  (128 * 36 * 4)              // bytes per array
#define GEMM_SMEM (4 * ARR_B)              // 73,728 B -> 2 CTAs/SM

__device__ __forceinline__ void gemm_core(
    const uint4* __restrict__ A4h, const uint4* __restrict__ A4l,
    const uint4* __restrict__ B4h, const uint4* __restrict__ B4l,
    u32* smem, float c[16][4])
{
    const int tid  = threadIdx.x;
    const int w    = tid >> 5;
    const int lane = tid & 31;

    const int arow = 16 * w + (lane & 7) + 8 * ((lane >> 3) & 1);
    const int acol = 4 * (lane >> 4);
    const int brow = (lane & 7) + 8 * (lane >> 4);
    const int bcol = 4 * ((lane >> 3) & 1);

    const u32 sb  = sptr(smem);
    const u32 aHb = sb + (u32)(arow * 36 + acol) * 4;
    const u32 bHb = sb + 2 * ARR_B + (u32)(brow * 36 + bcol) * 4;

    for (int kt = 0; kt < 8; kt++) {
        #pragma unroll
        for (int it = 0; it < 4; it++) {
            int e = tid + it * 256;
            int row = e >> 3, c4 = e & 7;
            u32 so = sb + (u32)(row * 36 + 4 * c4) * 4;
            size_t go = (size_t)row * 64 + kt * 8 + c4;
            cpasync16(so,             &A4h[go]);
            cpasync16(so + ARR_B,     &A4l[go]);
            cpasync16(so + 2 * ARR_B, &B4h[go]);
            cpasync16(so + 3 * ARR_B, &B4l[go]);
        }
        asm volatile("cp.async.commit_group;");
        asm volatile("cp.async.wait_group 0;");
        __syncthreads();

        #pragma unroll
        for (int ch = 0; ch < 4; ch++) {
            u32 aH[4], aL[4];
            ldsm4(aHb + 32 * ch,         aH);
            ldsm4(aHb + ARR_B + 32 * ch, aL);
            #pragma unroll
            for (int g2 = 0; g2 < 4; g2++) {       // groups of 2 n-tiles
                u32 bH[2][4], bL[2][4];
                #pragma unroll
                for (int j = 0; j < 2; j++) {
                    u32 off = 32 * ch + (u32)(2 * g2 + j) * (16 * 36 * 4);
                    ldsm4(bHb + off,         bH[j]);
                    ldsm4(bHb + ARR_B + off, bL[j]);
                }
                #pragma unroll
                for (int j = 0; j < 2; j++) {
                    int tp = 2 * g2 + j;
                    mma_bf16(c[2 * tp],     aH, bH[j]);
                    mma_bf16(c[2 * tp + 1], aH, bH[j] + 2);
                }
                #pragma unroll
                for (int j = 0; j < 2; j++) {
                    int tp = 2 * g2 + j;
                    mma_bf16(c[2 * tp],     aH, bL[j]);
                    mma_bf16(c[2 * tp + 1], aH, bL[j] + 2);
                }
                #pragma unroll
                for (int j = 0; j < 2; j++) {
                    int tp = 2 * g2 + j;
                    mma_bf16(c[2 * tp],     aL, bH[j]);
                    mma_bf16(c[2 * tp + 1], aL, bH[j] + 2);
                }
            }
        }
        __syncthreads();
    }
}

// ---------------------------------------------------------------------------
// Projections.
// ---------------------------------------------------------------------------
__global__ __launch_bounds__(256, 2) void proj_mma()
{
    extern __shared__ u32 sm[];

    const int z = blockIdx.z;
    int m0, n0;
    const u32 *Ah, *Al, *Bh, *Bl;
    if (z < 2) {
        m0 = blockIdx.y * 128; n0 = blockIdx.x * 128;
        Ah = g_xh + (size_t)z * XSZ; Al = g_xl + (size_t)z * XSZ;
        Bh = g_wh + (size_t)z * WSZ; Bl = g_wl + (size_t)z * WSZ;
    } else {
        m0 = blockIdx.x * 128; n0 = blockIdx.y * 128;
        Ah = g_wh + (size_t)2 * WSZ; Al = g_wl + (size_t)2 * WSZ;
        Bh = g_xh + (size_t)2 * XSZ; Bl = g_xl + (size_t)2 * XSZ;
    }

    float c[16][4] = {};
    gemm_core((const uint4*)Ah + (size_t)m0 * 64, (const uint4*)Al + (size_t)m0 * 64,
              (const uint4*)Bh + (size_t)n0 * 64, (const uint4*)Bl + (size_t)n0 * 64,
              sm, c);

    const int tid = threadIdx.x, w = tid >> 5, lane = tid & 31;
    const int lr = lane >> 2, lc = lane & 3;

    if (z < 2) {
        u32* oh = z ? g_kh : g_qh;
        u32* ol = z ? g_kl : g_ql;
        const float sc = z ? 1.0f : 0.125f;
        #pragma unroll
        for (int t = 0; t < 16; t++) {
            int ng = n0 + 8 * t + 2 * lc;
            int h = ng >> 6, pidx = (ng & 63) >> 1;
            #pragma unroll
            for (int half = 0; half < 2; half++) {
                int m = m0 + 16 * w + lr + 8 * half;
                int b = m >> 11, l = m & 2047;
                size_t base = ((size_t)(b * NH + h) * SEQ + l) * 32 + pidx;
                u32 H, L;
                split2(c[t][2 * half] * sc, c[t][2 * half + 1] * sc, H, L);
                oh[base] = H; ol[base] = L;
            }
        }
    } else {
        #pragma unroll
        for (int t = 0; t < 16; t++) {
            int kg = n0 + 8 * t + 2 * lc;
            int b = kg >> 11, l = kg & 2047;
            #pragma unroll
            for (int half = 0; half < 2; half++) {
                int dg = m0 + 16 * w + lr + 8 * half;
                int h = dg >> 6, hd = dg & 63;
                size_t base = ((size_t)(b * NH + h) * HDIM + hd) * 1024 + (l >> 1);
                u32 H, L;
                split2(c[t][2 * half], c[t][2 * half + 1], H, L);
                g_vh[base] = H; g_vl[base] = L;
            }
        }
    }
}

// ---------------------------------------------------------------------------
// Attention: unchanged from R16 (validated).
// ---------------------------------------------------------------------------
#define QROW 36
#define ATTN_SMEM ((2 * 128 * QROW + 4 * 64 * QROW + 64) * 4)   // 73,984 B

__global__ __launch_bounds__(256, 2) void attn_kernel(const int* __restrict__ amask)
{
    extern __shared__ u32 smu[];
    u32* qh = smu;
    u32* ql = qh + 128 * QROW;
    u32* kh = ql + 128 * QROW;
    u32* kl = kh + 64 * QROW;
    u32* vh = kl + 64 * QROW;
    u32* vl = vh + 64 * QROW;
    int* m_s = (int*)(vl + 64 * QROW);

    const int q0   = blockIdx.x * 128;
    const int h    = blockIdx.y;
    const int b    = blockIdx.z;
    const int tid  = threadIdx.x;
    const int w    = tid >> 5;
    const int lane = tid & 31;
    const int lr   = lane >> 2, lc = lane & 3;

    const int arow = 16 * w + (lane & 7) + 8 * ((lane >> 3) & 1);
    const int acol = 4 * (lane >> 4);
    const int brow = (lane & 7) + 8 * (lane >> 4);
    const int bcol = 4 * ((lane >> 3) & 1);

    const u32 qHb = sptr(qh) + (u32)(arow * QROW + acol) * 4;
    const u32 qLb = sptr(ql) + (u32)(arow * QROW + acol) * 4;
    const u32 kHb = sptr(kh) + (u32)(brow * QROW + bcol) * 4;
    const u32 kLb = sptr(kl) + (u32)(brow * QROW + bcol) * 4;
    const u32 vHb = sptr(vh) + (u32)(brow * QROW + bcol) * 4;
    const u32 vLb = sptr(vl) + (u32)(brow * QROW + bcol) * 4;

    const size_t bh  = (size_t)(b * NH + h);
    const size_t qb4 = (bh * SEQ + q0) * 8;
    const size_t kb4 = (bh * SEQ) * 8;
    const size_t vb4 = (bh * HDIM) * 256;

    #pragma unroll
    for (int it = 0; it < 4; it++) {
        int e = tid + it * 256;
        int row = e >> 3, c4 = e & 7;
        *(uint4*)&qh[row * QROW + 4 * c4] = ((const uint4*)g_qh)[qb4 + e];
        *(uint4*)&ql[row * QROW + 4 * c4] = ((const uint4*)g_ql)[qb4 + e];
    }

    float o[8][4] = {};
    float lrow0 = 0.f, lrow1 = 0.f;

    for (int kt = 0; kt < SEQ / 64; kt++) {
        __syncthreads();
        #pragma unroll
        for (int it = 0; it < 2; it++) {
            int e = tid + it * 256;
            int row = e >> 3, c4 = e & 7;
            *(uint4*)&kh[row * QROW + 4 * c4] = ((const uint4*)g_kh)[kb4 + kt * 512 + e];
            *(uint4*)&kl[row * QROW + 4 * c4] = ((const uint4*)g_kl)[kb4 + kt * 512 + e];
            *(uint4*)&vh[row * QROW + 4 * c4] = ((const uint4*)g_vh)[vb4 + row * 256 + kt * 8 + c4];
            *(uint4*)&vl[row * QROW + 4 * c4] = ((const uint4*)g_vl)[vb4 + row * 256 + kt * 8 + c4];
        }
        if (tid < 64) m_s[tid] = amask[b * SEQ + kt * 64 + tid];
        __syncthreads();

        // ---- S = Q K^T ----
        float s[8][4] = {};
        #pragma unroll
        for (int ch = 0; ch < 4; ch++) {
            u32 aH[4], aL[4];
            ldsm4(qHb + 32 * ch, aH);
            ldsm4(qLb + 32 * ch, aL);
            #pragma unroll
            for (int half = 0; half < 2; half++) {
                u32 bH[2][4], bL[2][4];
                #pragma unroll
                for (int j = 0; j < 2; j++) {
                    u32 off = 32 * ch + (u32)(2 * half + j) * (16 * QROW * 4);
                    ldsm4(kHb + off, bH[j]);
                    ldsm4(kLb + off, bL[j]);
                }
                #pragma unroll
                for (int j = 0; j < 2; j++) {
                    int tp = 2 * half + j;
                    mma_bf16(s[2 * tp],     aH, bH[j]);
                    mma_bf16(s[2 * tp + 1], aH, bH[j] + 2);
                }
                #pragma unroll
                for (int j = 0; j < 2; j++) {
                    int tp = 2 * half + j;
                    mma_bf16(s[2 * tp],     aH, bL[j]);
                    mma_bf16(s[2 * tp + 1], aH, bL[j] + 2);
                }
                #pragma unroll
                for (int j = 0; j < 2; j++) {
                    int tp = 2 * half + j;
                    mma_bf16(s[2 * tp],     aL, bH[j]);
                    mma_bf16(s[2 * tp + 1], aL, bH[j] + 2);
                }
            }
        }

        // ---- exp + mask + row sums + register P split ----
        u32 pH0[8], pH1[8], pL0[8], pL1[8];
        #pragma unroll
        for (int t = 0; t < 8; t++) {
            int c0 = 8 * t + 2 * lc;
            bool d0 = (m_s[c0] == 0), d1 = (m_s[c0 + 1] == 0);
            float p0 = d0 ? 0.f : __expf(s[t][0]);
            float p1 = d1 ? 0.f : __expf(s[t][1]);
            float p2 = d0 ? 0.f : __expf(s[t][2]);
            float p3 = d1 ? 0.f : __expf(s[t][3]);
            lrow0 += p0 + p1;
            lrow1 += p2 + p3;
            float h0 = bfround(p0), h1 = bfround(p1);
            float h2 = bfround(p2), h3 = bfround(p3);
            pH0[t] = bfpack(h0, h1);           pH1[t] = bfpack(h2, h3);
            pL0[t] = bfpack(p0 - h0, p1 - h1); pL1[t] = bfpack(p2 - h2, p3 - h3);
        }

        // ---- O += P V ----
        #pragma unroll
        for (int ch = 0; ch < 4; ch++) {
            u32 aH[4] = { pH0[2 * ch], pH1[2 * ch], pH0[2 * ch + 1], pH1[2 * ch + 1] };
            u32 aL[4] = { pL0[2 * ch], pL1[2 * ch], pL0[2 * ch + 1], pL1[2 * ch + 1] };
            #pragma unroll
            for (int half = 0; half < 2; half++) {
                u32 bH[2][4], bL[2][4];
                #pragma unroll
                for (int j = 0; j < 2; j++) {
                    u32 off = 32 * ch + (u32)(2 * half + j) * (16 * QROW * 4);
                    ldsm4(vHb + off, bH[j]);
                    ldsm4(vLb + off, bL[j]);
                }
                #pragma unroll
                for (int j = 0; j < 2; j++) {
                    int tp = 2 * half + j;
                    mma_bf16(o[2 * tp],     aH, bH[j]);
                    mma_bf16(o[2 * tp + 1], aH, bH[j] + 2);
                }
                #pragma unroll
                for (int j = 0; j < 2; j++) {
                    int tp = 2 * half + j;
                    mma_bf16(o[2 * tp],     aH, bL[j]);
                    mma_bf16(o[2 * tp + 1], aH, bL[j] + 2);
                }
                #pragma unroll
                for (int j = 0; j < 2; j++) {
                    int tp = 2 * half + j;
                    mma_bf16(o[2 * tp],     aL, bH[j]);
                    mma_bf16(o[2 * tp + 1], aL, bH[j] + 2);
                }
            }
        }
    }

    lrow0 += __shfl_xor_sync(0xffffffffu, lrow0, 1);
    lrow0 += __shfl_xor_sync(0xffffffffu, lrow0, 2);
    lrow1 += __shfl_xor_sync(0xffffffffu, lrow1, 1);
    lrow1 += __shfl_xor_sync(0xffffffffu, lrow1, 2);
    float inv0 = 1.f / lrow0, inv1 = 1.f / lrow1;

    const int r0 = 16 * w + lr;
    const size_t a0 = (size_t)(b * SEQ + q0 + r0) * 256 + h * 32;
    const size_t a1 = (size_t)(b * SEQ + q0 + r0 + 8) * 256 + h * 32;
    #pragma unroll
    for (int t = 0; t < 8; t++) {
        u32 H, L;
        split2(o[t][0] * inv0, o[t][1] * inv0, H, L);
        g_avh[a0 + 4 * t + lc] = H; g_avl[a0 + 4 * t + lc] = L;
        split2(o[t][2] * inv1, o[t][3] * inv1, H, L);
        g_avh[a1 + 4 * t + lc] = H; g_avl[a1 + 4 * t + lc] = L;
    }
}

// ---------------------------------------------------------------------------
// Output projection.
// ---------------------------------------------------------------------------
__global__ __launch_bounds__(256, 2) void out_mma(float* __restrict__ out)
{
    extern __shared__ u32 sm[];

    const int n0 = blockIdx.x * 128;
    const int m0 = blockIdx.y * 128;

    float c[16][4] = {};
    gemm_core((const uint4*)g_avh + (size_t)m0 * 64,
              (const uint4*)g_avl + (size_t)m0 * 64,
              (const uint4*)(g_wh + (size_t)3 * WSZ) + (size_t)n0 * 64,
              (const uint4*)(g_wl + (size_t)3 * WSZ) + (size_t)n0 * 64,
              sm, c);

    const int tid = threadIdx.x, w = tid >> 5, lane = tid & 31;
    const int lr = lane >> 2, lc = lane & 3;
    #pragma unroll
    for (int t = 0; t < 16; t++) {
        int col = n0 + 8 * t + 2 * lc;
        #pragma unroll
        for (int half = 0; half < 2; half++) {
            int m = m0 + 16 * w + lr + 8 * half;
            *(float2*)&out[(size_t)m * DIM + col] =
                make_float2(c[t][2 * half], c[t][2 * half + 1]);
        }
    }
}

// ---------------------------------------------------------------------------
extern "C" void kernel_launch(void* const* d_in, const int* in_sizes, int n_in,
                              void* d_out, int out_size)
{
    const float* query = (const float*)d_in[0];
    const float* key   = (const float*)d_in[1];
    const float* value = (const float*)d_in[2];
    const float* Wq    = (const float*)d_in[3];
    const float* Wk    = (const float*)d_in[4];
    const float* Wv    = (const float*)d_in[5];
    const float* Wo    = (const float*)d_in[6];
    const int*   amask = (const int*)d_in[7];
    float*       out   = (float*)d_out;

    (void)in_sizes; (void)n_in; (void)out_size;

    split_kernel<<<dim3(2048, 7), 256>>>(query, key, value, Wq, Wk, Wv, Wo);

    cudaFuncSetAttribute(proj_mma, cudaFuncAttributeMaxDynamicSharedMemorySize, GEMM_SMEM);
    proj_mma<<<dim3(4, 64, 3), 256, GEMM_SMEM>>>();

    cudaFuncSetAttribute(attn_kernel, cudaFuncAttributeMaxDynamicSharedMemorySize, ATTN_SMEM);
    attn_kernel<<<dim3(SEQ / 128, NH, Bz), 256, ATTN_SMEM>>>(amask);

    cudaFuncSetAttribute(out_mma, cudaFuncAttributeMaxDynamicSharedMemorySize, GEMM_SMEM);
    out_mma<<<dim3(4, 64), 256, GEMM_SMEM>>>(out);
}